// round 1
// baseline (speedup 1.0000x reference)
#include <cuda_runtime.h>
#include <math.h>
#include <stdint.h>

#define D_NUM 1500
#define P_NUM 4500
#define NTOT  6000
#define EMB   128
#define CAP_DD 64    // ELL width for rows over a 1500-col domain (mean nnz ~7.5)
#define CAP_PP 128   // ELL width for rows over a 4500-col domain (mean nnz ~22.5)
#define DB (D_NUM*EMB)
#define PB (P_NUM*EMB)

// ---------------- scratch (static __device__, no allocs) ----------------
__device__ int g_idx2[D_NUM*CAP_DD]; __device__ int g_len2[D_NUM];
__device__ int g_idx4[D_NUM*CAP_DD]; __device__ int g_len4[D_NUM];
__device__ int g_idx3[P_NUM*CAP_PP]; __device__ int g_len3[P_NUM];
__device__ int g_idxR[D_NUM*CAP_PP]; __device__ int g_lenR[D_NUM];
__device__ int g_idxRT[P_NUM*CAP_DD]; __device__ int g_curRT[P_NUM];

__device__ float g_dinv2[D_NUM], g_cinv2[D_NUM];
__device__ float g_dinv3[P_NUM], g_cinv3[P_NUM];
__device__ float g_dinv4[D_NUM];
__device__ float g_dinvRd[D_NUM], g_cinvRd[D_NUM];
__device__ float g_dinvRp[P_NUM], g_cinvRp[P_NUM];

__device__ float g_dru_str[DB], g_pro_str[PB];
__device__ float g_nei2[DB],    g_nei3[PB];
__device__ float g_emb2[DB],    g_emb3[PB],  g_emb4[DB];
__device__ float g_cur[PB],     g_nxt[PB],   g_acc[PB];
__device__ float g_temd[DB],    g_temp[PB];
__device__ float g_one_emb[DB], g_two_all[PB], g_one_all[DB], g_two_emb[PB];
__device__ float g_bd1[DB],     g_bp1[PB],   g_bp2[PB];
__device__ float g_accd[DB],    g_accp[PB];
__device__ float g_dru_int[DB], g_pro_int[PB];
__device__ float g_tmpp[PB],    g_Wc[EMB*EMB];
__device__ float g_fin_d[DB],   g_fin_p[PB];
__device__ float g_wdrug[D_NUM], g_wdrel[D_NUM], g_wdsim[D_NUM];
__device__ float g_wpro[P_NUM],  g_wprel[P_NUM];
__device__ float g_y[(size_t)D_NUM*P_NUM];
__device__ double g_stats[2];

// ---------------- kernels ----------------

// One-pass ordered compaction of a sub-block of a 6000-stride 0/1 matrix into
// padded ELL rows. Deterministic (ballot-based, in-order).
__global__ void k_ell_fill(const float* __restrict__ base, int row0, int col0,
                           int ncols, int cap, int* __restrict__ idx,
                           int* __restrict__ len) {
    int r = blockIdx.x;
    const float* row = base + (size_t)(row0 + r) * NTOT + col0;
    __shared__ int s_warp[8];
    __shared__ int s_base;
    if (threadIdx.x == 0) s_base = 0;
    __syncthreads();
    int rb = r * cap;
    for (int c0 = 0; c0 < ncols; c0 += 256) {
        int c = c0 + threadIdx.x;
        bool pred = (c < ncols) && (row[c] == 1.0f);
        unsigned m = __ballot_sync(0xffffffffu, pred);
        int lane = threadIdx.x & 31, w = threadIdx.x >> 5;
        if (lane == 0) s_warp[w] = __popc(m);
        __syncthreads();
        int off = s_base;
        for (int i = 0; i < w; i++) off += s_warp[i];
        int tot = 0;
        for (int i = 0; i < 8; i++) tot += s_warp[i];
        off += __popc(m & ((1u << lane) - 1));
        if (pred && off < cap) idx[rb + off] = c;
        __syncthreads();
        if (threadIdx.x == 0) s_base += tot;
        __syncthreads();
    }
    if (threadIdx.x == 0) len[r] = min(s_base, cap);
}

// Build ELL of R^T from ELL of R (atomics, then sorted for determinism).
__global__ void k_rt_fill() {
    int r = blockIdx.x;
    int L = g_lenR[r];
    for (int p = threadIdx.x; p < L; p += blockDim.x) {
        int c = g_idxR[r * CAP_PP + p];
        int pos = atomicAdd(&g_curRT[c], 1);
        if (pos < CAP_DD) g_idxRT[c * CAP_DD + pos] = r;
    }
}
__global__ void k_rt_sort() {
    int c = blockIdx.x * blockDim.x + threadIdx.x;
    if (c >= P_NUM) return;
    int L = min(g_curRT[c], CAP_DD);
    g_curRT[c] = L;
    int* a = &g_idxRT[c * CAP_DD];
    for (int i = 1; i < L; i++) {
        int v = a[i]; int j = i - 1;
        while (j >= 0 && a[j] > v) { a[j + 1] = a[j]; j--; }
        a[j + 1] = v;
    }
}

__global__ void k_scales(const int* __restrict__ len, float* __restrict__ dinv,
                         float* __restrict__ cinv, int n) {
    int i = blockIdx.x * blockDim.x + threadIdx.x;
    if (i >= n) return;
    int d = len[i];
    dinv[i] = d > 0 ? 1.0f / sqrtf((float)d) : 0.0f;
    if (cinv) cinv[i] = d > 0 ? 1.0f / (float)d : 0.0f;
}

// C(n x 128) = A(n x k) @ W(k x 128) [+ bias]; optional duplicate output C2.
__global__ void k_gemm128(const float* __restrict__ A, int n, int k,
                          const float* __restrict__ W, const float* __restrict__ bias,
                          float* __restrict__ C, float* __restrict__ C2) {
    __shared__ float sA[8 * 512];
    int r0 = blockIdx.x * 8;
    for (int i = threadIdx.x; i < 8 * k; i += 128) {
        int rr = i / k, kk = i - rr * k;
        int gr = r0 + rr;
        sA[rr * 512 + kk] = (gr < n) ? A[(size_t)gr * k + kk] : 0.0f;
    }
    __syncthreads();
    int c = threadIdx.x;
    float acc[8];
#pragma unroll
    for (int rr = 0; rr < 8; rr++) acc[rr] = 0.0f;
    for (int kk = 0; kk < k; kk++) {
        float w = W[(size_t)kk * EMB + c];
#pragma unroll
        for (int rr = 0; rr < 8; rr++) acc[rr] += sA[rr * 512 + kk] * w;
    }
    float b = bias ? bias[c] : 0.0f;
#pragma unroll
    for (int rr = 0; rr < 8; rr++) {
        int gr = r0 + rr;
        if (gr < n) {
            float v = acc[rr] + b;
            C[(size_t)gr * EMB + c] = v;
            if (C2) C2[(size_t)gr * EMB + c] = v;
        }
    }
}

// out[r,:] = rs[r] * sum_{j in row r} (cs?cs[j]:1) * x[j,:]; optional acc +=.
__global__ void k_spmm(const int* __restrict__ idx, const int* __restrict__ len,
                       int cap, const float* __restrict__ rs,
                       const float* __restrict__ cs, const float* __restrict__ x,
                       float* __restrict__ out, float* __restrict__ acc) {
    int r = blockIdx.x, c = threadIdx.x;
    int L = len[r];
    const int* ip = idx + (size_t)r * cap;
    float s = 0.0f;
    for (int p = 0; p < L; p++) {
        int j = __ldg(ip + p);
        float f = cs ? __ldg(cs + j) : 1.0f;
        s += f * __ldg(&x[(size_t)j * EMB + c]);
    }
    s *= rs[r];
    size_t o = (size_t)r * EMB + c;
    out[o] = s;
    if (acc) acc[o] += s;
}

__global__ void k_scale(float* __restrict__ dst, const float* __restrict__ src,
                        float a, int n) {
    int i = blockIdx.x * blockDim.x + threadIdx.x;
    if (i < n) dst[i] = src[i] * a;
}
__global__ void k_axpby(float* __restrict__ dst, const float* __restrict__ x,
                        const float* __restrict__ y, float a, float b, int n) {
    int i = blockIdx.x * blockDim.x + threadIdx.x;
    if (i < n) dst[i] = a * x[i] + b * y[i];
}

// s[r] = sum_c relu(emb[r,:] @ W[:,c] + B[c]) * H[c]
__global__ void k_att(const float* __restrict__ emb, const float* __restrict__ W,
                      const float* __restrict__ B, const float* __restrict__ H,
                      float* __restrict__ s) {
    int r = blockIdx.x, t = threadIdx.x;
    __shared__ float se[EMB];
    se[t] = emb[(size_t)r * EMB + t];
    __syncthreads();
    float d = 0.0f;
#pragma unroll 8
    for (int k = 0; k < EMB; k++) d += se[k] * W[k * EMB + t];
    float v = fmaxf(d + B[t], 0.0f) * H[t];
    for (int o = 16; o; o >>= 1) v += __shfl_down_sync(0xffffffffu, v, o);
    __shared__ float sw[4];
    if ((t & 31) == 0) sw[t >> 5] = v;
    __syncthreads();
    if (t == 0) s[r] = sw[0] + sw[1] + sw[2] + sw[3];
}

__global__ void k_logsoftmax(float* __restrict__ s, int n) {
    __shared__ float sh[1024];
    int t = threadIdx.x;
    float m = -1e30f;
    for (int i = t; i < n; i += 1024) m = fmaxf(m, s[i]);
    sh[t] = m; __syncthreads();
    for (int o = 512; o; o >>= 1) { if (t < o) sh[t] = fmaxf(sh[t], sh[t + o]); __syncthreads(); }
    float mall = sh[0]; __syncthreads();
    float sum = 0.0f;
    for (int i = t; i < n; i += 1024) sum += expf(s[i] - mall);
    sh[t] = sum; __syncthreads();
    for (int o = 512; o; o >>= 1) { if (t < o) sh[t] += sh[t + o]; __syncthreads(); }
    float lse = mall + logf(sh[0]);
    for (int i = t; i < n; i += 1024) s[i] -= lse;
}

__global__ void k_comb_dru() {
    int i = blockIdx.x * blockDim.x + threadIdx.x;
    if (i >= DB) return;
    int r = i >> 7;
    float wa = g_wdrug[r], wb = g_wdrel[r], wc = g_wdsim[r];
    float a = wa / (wa + wb + wc);
    float b = wb / (a + wb + wc);
    float c = 1.0f - a - b;
    g_fin_d[i] = a * g_dru_int[i] + b * g_emb2[i] + c * g_emb4[i];
}
__global__ void k_comb_pro() {
    int i = blockIdx.x * blockDim.x + threadIdx.x;
    if (i >= PB) return;
    int r = i >> 7;
    float wa = g_wpro[r], wb = g_wprel[r];
    float pa = wa / (wa + wb);
    g_fin_p[i] = pa * g_pro_int[i] + (1.0f - pa) * g_emb3[i];
}

// Y = fin_d @ fin_p^T with fused fp64 sum / sumsq for standardization.
__global__ void k_final_gemm() {
    __shared__ float As[64][33];
    __shared__ float Bs[64][33];
    int bi = blockIdx.y * 64, bj = blockIdx.x * 64;
    int t = threadIdx.x;
    int tx = t & 15, ty = t >> 4;
    float acc[4][4];
#pragma unroll
    for (int i = 0; i < 4; i++)
#pragma unroll
        for (int j = 0; j < 4; j++) acc[i][j] = 0.0f;
    for (int k0 = 0; k0 < EMB; k0 += 32) {
        for (int i = t; i < 64 * 32; i += 256) {
            int rr = i >> 5, kk = i & 31;
            int gr = bi + rr;
            As[rr][kk] = (gr < D_NUM) ? g_fin_d[(size_t)gr * EMB + k0 + kk] : 0.0f;
        }
        for (int i = t; i < 64 * 32; i += 256) {
            int rr = i >> 5, kk = i & 31;
            int gr = bj + rr;
            Bs[rr][kk] = (gr < P_NUM) ? g_fin_p[(size_t)gr * EMB + k0 + kk] : 0.0f;
        }
        __syncthreads();
#pragma unroll
        for (int kk = 0; kk < 32; kk++) {
            float ra[4], rb[4];
#pragma unroll
            for (int i = 0; i < 4; i++) ra[i] = As[ty * 4 + i][kk];
#pragma unroll
            for (int j = 0; j < 4; j++) rb[j] = Bs[tx * 4 + j][kk];
#pragma unroll
            for (int i = 0; i < 4; i++)
#pragma unroll
                for (int j = 0; j < 4; j++) acc[i][j] += ra[i] * rb[j];
        }
        __syncthreads();
    }
    double ls = 0.0, lq = 0.0;
#pragma unroll
    for (int i = 0; i < 4; i++) {
        int gi = bi + ty * 4 + i;
#pragma unroll
        for (int j = 0; j < 4; j++) {
            int gj = bj + tx * 4 + j;
            if (gi < D_NUM && gj < P_NUM) {
                float v = acc[i][j];
                g_y[(size_t)gi * P_NUM + gj] = v;
                ls += v;
                lq += (double)v * v;
            }
        }
    }
    __shared__ double sd[256];
    sd[t] = ls; __syncthreads();
    for (int o = 128; o; o >>= 1) { if (t < o) sd[t] += sd[t + o]; __syncthreads(); }
    if (t == 0) atomicAdd(&g_stats[0], sd[0]);
    __syncthreads();
    sd[t] = lq; __syncthreads();
    for (int o = 128; o; o >>= 1) { if (t < o) sd[t] += sd[t + o]; __syncthreads(); }
    if (t == 0) atomicAdd(&g_stats[1], sd[0]);
}

__global__ void k_finalize(float* __restrict__ out) {
    const double n = (double)D_NUM * (double)P_NUM;
    double sum = g_stats[0], sq = g_stats[1];
    double mean = sum / n;
    double var = (sq - sum * sum / n) / (n - 1.0);
    float istd = (float)(1.0 / sqrt(var));
    float mu = (float)mean;
    size_t N = (size_t)D_NUM * P_NUM;
    for (size_t i = (size_t)blockIdx.x * blockDim.x + threadIdx.x; i < N;
         i += (size_t)gridDim.x * blockDim.x) {
        float z = (g_y[i] - mu) * istd;
        out[i] = 1.0f / (1.0f + expf(-z));
    }
}

// ---------------- host launcher ----------------
extern "C" void kernel_launch(void* const* d_in, const int* in_sizes, int n_in,
                              void* d_out, int out_size) {
    const float* A                 = (const float*)d_in[0];
    const float* drug_structure    = (const float*)d_in[1];
    const float* protein_structure = (const float*)d_in[2];
    const float* lin_drug_w = (const float*)d_in[3];
    const float* lin_drug_b = (const float*)d_in[4];
    const float* lin_pro_w  = (const float*)d_in[5];
    const float* lin_pro_b  = (const float*)d_in[6];
    const float* p_weight   = (const float*)d_in[7];
    const float* d_weight_i = (const float*)d_in[8];
    const float* pd_weight_p = (const float*)d_in[9];
    const float* pd_weight_d = (const float*)d_in[10];
    const float* dp_weight_p = (const float*)d_in[11];
    const float* WA_drug = (const float*)d_in[12];
    const float* BA_drug = (const float*)d_in[13];
    const float* HA_drug = (const float*)d_in[14];
    const float* WB_drug = (const float*)d_in[15];
    const float* BB_drug = (const float*)d_in[16];
    const float* HB_drug = (const float*)d_in[17];
    const float* WA_pro = (const float*)d_in[18];
    const float* BA_pro = (const float*)d_in[19];
    const float* HA_pro = (const float*)d_in[20];
    const float* WB_pro = (const float*)d_in[21];
    const float* BB_pro = (const float*)d_in[22];
    const float* HB_pro = (const float*)d_in[23];
    const float* WA_sim = (const float*)d_in[24];
    const float* BA_sim = (const float*)d_in[25];
    const float* HA_sim = (const float*)d_in[26];
    float* out = (float*)d_out;
    (void)in_sizes; (void)n_in; (void)out_size;

    void* tp;
#define SYMI(p, s) cudaGetSymbolAddress(&tp, s); int* p = (int*)tp;
#define SYMF(p, s) cudaGetSymbolAddress(&tp, s); float* p = (float*)tp;
#define SYMD(p, s) cudaGetSymbolAddress(&tp, s); double* p = (double*)tp;
    SYMI(p_idx2, g_idx2)  SYMI(p_len2, g_len2)
    SYMI(p_idx3, g_idx3)  SYMI(p_len3, g_len3)
    SYMI(p_idx4, g_idx4)  SYMI(p_len4, g_len4)
    SYMI(p_idxR, g_idxR)  SYMI(p_lenR, g_lenR)
    SYMI(p_idxRT, g_idxRT) SYMI(p_curRT, g_curRT)
    SYMF(p_dinv2, g_dinv2) SYMF(p_cinv2, g_cinv2)
    SYMF(p_dinv3, g_dinv3) SYMF(p_cinv3, g_cinv3)
    SYMF(p_dinv4, g_dinv4)
    SYMF(p_dinvRd, g_dinvRd) SYMF(p_cinvRd, g_cinvRd)
    SYMF(p_dinvRp, g_dinvRp) SYMF(p_cinvRp, g_cinvRp)
    SYMF(p_dru_str, g_dru_str) SYMF(p_pro_str, g_pro_str)
    SYMF(p_nei2, g_nei2) SYMF(p_nei3, g_nei3)
    SYMF(p_emb2, g_emb2) SYMF(p_emb3, g_emb3) SYMF(p_emb4, g_emb4)
    SYMF(p_cur, g_cur) SYMF(p_nxt, g_nxt) SYMF(p_acc, g_acc)
    SYMF(p_temd, g_temd) SYMF(p_temp, g_temp)
    SYMF(p_one_emb, g_one_emb) SYMF(p_two_all, g_two_all)
    SYMF(p_one_all, g_one_all) SYMF(p_two_emb, g_two_emb)
    SYMF(p_bd1, g_bd1) SYMF(p_bp1, g_bp1) SYMF(p_bp2, g_bp2)
    SYMF(p_accd, g_accd) SYMF(p_accp, g_accp)
    SYMF(p_dru_int, g_dru_int) SYMF(p_pro_int, g_pro_int)
    SYMF(p_tmpp, g_tmpp) SYMF(p_Wc, g_Wc)
    SYMF(p_wdrug, g_wdrug) SYMF(p_wdrel, g_wdrel) SYMF(p_wdsim, g_wdsim)
    SYMF(p_wpro, g_wpro) SYMF(p_wprel, g_wprel)
    SYMD(p_stats, g_stats)

    const size_t NN = (size_t)NTOT * NTOT;

    // ---- phase A: sparse structure extraction (single pass over A blocks)
    k_ell_fill<<<D_NUM, 256>>>(A + 2 * NN, 0, 0, D_NUM, CAP_DD, p_idx2, p_len2);
    k_ell_fill<<<P_NUM, 256>>>(A + 3 * NN, D_NUM, D_NUM, P_NUM, CAP_PP, p_idx3, p_len3);
    k_ell_fill<<<D_NUM, 256>>>(A + 4 * NN, 0, 0, D_NUM, CAP_DD, p_idx4, p_len4);
    k_ell_fill<<<D_NUM, 256>>>(A, 0, D_NUM, P_NUM, CAP_PP, p_idxR, p_lenR);
    cudaMemsetAsync(p_curRT, 0, P_NUM * sizeof(int), 0);
    cudaMemsetAsync(p_stats, 0, 2 * sizeof(double), 0);
    k_rt_fill<<<D_NUM, 128>>>();
    k_rt_sort<<<(P_NUM + 255) / 256, 256>>>();
    k_scales<<<(D_NUM + 255) / 256, 256>>>(p_len2, p_dinv2, p_cinv2, D_NUM);
    k_scales<<<(P_NUM + 255) / 256, 256>>>(p_len3, p_dinv3, p_cinv3, P_NUM);
    k_scales<<<(D_NUM + 255) / 256, 256>>>(p_len4, p_dinv4, nullptr, D_NUM);
    k_scales<<<(D_NUM + 255) / 256, 256>>>(p_lenR, p_dinvRd, p_cinvRd, D_NUM);
    k_scales<<<(P_NUM + 255) / 256, 256>>>(p_curRT, p_dinvRp, p_cinvRp, P_NUM);

    // ---- phase B: feature lifts
    k_gemm128<<<(D_NUM + 7) / 8, 128>>>(drug_structure, D_NUM, 160, lin_drug_w, lin_drug_b, p_dru_str, nullptr);
    k_gemm128<<<(P_NUM + 7) / 8, 128>>>(protein_structure, P_NUM, 512, lin_pro_w, lin_pro_b, p_pro_str, nullptr);

    // ---- phase C: rel_emb towers (layer = 3)
    // graph 2 (drug relation)
    k_spmm<<<D_NUM, 128>>>(p_idx2, p_len2, CAP_DD, p_cinv2, nullptr, p_dru_str, p_nei2, nullptr);
    k_gemm128<<<(D_NUM + 7) / 8, 128>>>(p_dru_str, D_NUM, 128, d_weight_i, nullptr, p_cur, p_acc);
    k_spmm<<<D_NUM, 128>>>(p_idx2, p_len2, CAP_DD, p_dinv2, p_dinv2, p_cur, p_nxt, p_acc);
    k_spmm<<<D_NUM, 128>>>(p_idx2, p_len2, CAP_DD, p_dinv2, p_dinv2, p_nxt, p_cur, p_acc);
    k_spmm<<<D_NUM, 128>>>(p_idx2, p_len2, CAP_DD, p_dinv2, p_dinv2, p_cur, p_nxt, p_acc);
    k_scale<<<(DB + 255) / 256, 256>>>(p_emb2, p_acc, 0.25f, DB);
    // graph 3 (protein relation)
    k_spmm<<<P_NUM, 128>>>(p_idx3, p_len3, CAP_PP, p_cinv3, nullptr, p_pro_str, p_nei3, nullptr);
    k_gemm128<<<(P_NUM + 7) / 8, 128>>>(p_pro_str, P_NUM, 128, p_weight, nullptr, p_cur, p_acc);
    k_spmm<<<P_NUM, 128>>>(p_idx3, p_len3, CAP_PP, p_dinv3, p_dinv3, p_cur, p_nxt, p_acc);
    k_spmm<<<P_NUM, 128>>>(p_idx3, p_len3, CAP_PP, p_dinv3, p_dinv3, p_nxt, p_cur, p_acc);
    k_spmm<<<P_NUM, 128>>>(p_idx3, p_len3, CAP_PP, p_dinv3, p_dinv3, p_cur, p_nxt, p_acc);
    k_scale<<<(PB + 255) / 256, 256>>>(p_emb3, p_acc, 0.25f, PB);
    // graph 4 (drug similarity; nei unused downstream)
    k_gemm128<<<(D_NUM + 7) / 8, 128>>>(p_dru_str, D_NUM, 128, d_weight_i, nullptr, p_cur, p_acc);
    k_spmm<<<D_NUM, 128>>>(p_idx4, p_len4, CAP_DD, p_dinv4, p_dinv4, p_cur, p_nxt, p_acc);
    k_spmm<<<D_NUM, 128>>>(p_idx4, p_len4, CAP_DD, p_dinv4, p_dinv4, p_nxt, p_cur, p_acc);
    k_spmm<<<D_NUM, 128>>>(p_idx4, p_len4, CAP_DD, p_dinv4, p_dinv4, p_cur, p_nxt, p_acc);
    k_scale<<<(DB + 255) / 256, 256>>>(p_emb4, p_acc, 0.25f, DB);

    // ---- phase D: cross-domain neighbor means
    k_spmm<<<D_NUM, 128>>>(p_idxR, p_lenR, CAP_PP, p_cinvRd, nullptr, p_nei3, p_temd, nullptr);
    k_spmm<<<P_NUM, 128>>>(p_idxRT, p_curRT, CAP_DD, p_cinvRp, nullptr, p_nei2, p_temp, nullptr);

    // ---- phase E: mixed features
    k_axpby<<<(DB + 255) / 256, 256>>>(p_one_all, p_dru_str, p_temd, 0.8f, 0.2f, DB);
    k_axpby<<<(PB + 255) / 256, 256>>>(p_tmpp, p_pro_str, p_temp, 0.8f, 0.2f, PB);
    k_gemm128<<<16, 128>>>(dp_weight_p, 128, 128, pd_weight_d, nullptr, p_Wc, nullptr);
    k_gemm128<<<(P_NUM + 7) / 8, 128>>>(p_tmpp, P_NUM, 128, p_Wc, nullptr, p_two_all, nullptr);
    k_gemm128<<<(D_NUM + 7) / 8, 128>>>(p_dru_str, D_NUM, 128, pd_weight_d, nullptr, p_one_emb, p_accd);
    k_gemm128<<<(P_NUM + 7) / 8, 128>>>(p_pro_str, P_NUM, 128, pd_weight_p, nullptr, p_two_emb, p_accp);

    // ---- phase F: bipartite GCNs (only needed half accumulated)
    // dru_int = (x_d + S x_p + S S^T x_d + S S^T S x_p) / 4, x_d=one_emb, x_p=two_all
    k_spmm<<<D_NUM, 128>>>(p_idxR, p_lenR, CAP_PP, p_dinvRd, p_dinvRp, p_two_all, p_bd1, p_accd);
    k_spmm<<<P_NUM, 128>>>(p_idxRT, p_curRT, CAP_DD, p_dinvRp, p_dinvRd, p_one_emb, p_bp1, nullptr);
    k_spmm<<<P_NUM, 128>>>(p_idxRT, p_curRT, CAP_DD, p_dinvRp, p_dinvRd, p_bd1, p_bp2, nullptr);
    k_spmm<<<D_NUM, 128>>>(p_idxR, p_lenR, CAP_PP, p_dinvRd, p_dinvRp, p_bp1, p_bd1, p_accd);
    k_spmm<<<D_NUM, 128>>>(p_idxR, p_lenR, CAP_PP, p_dinvRd, p_dinvRp, p_bp2, p_bd1, p_accd);
    k_scale<<<(DB + 255) / 256, 256>>>(p_dru_int, p_accd, 0.25f, DB);
    // pro_int = (x_p + S^T x_d + S^T S x_p + S^T S S^T x_d) / 4, x_d=one_all, x_p=two_emb
    k_spmm<<<P_NUM, 128>>>(p_idxRT, p_curRT, CAP_DD, p_dinvRp, p_dinvRd, p_one_all, p_bp1, p_accp);
    k_spmm<<<D_NUM, 128>>>(p_idxR, p_lenR, CAP_PP, p_dinvRd, p_dinvRp, p_two_emb, p_bd1, nullptr);
    k_spmm<<<P_NUM, 128>>>(p_idxRT, p_curRT, CAP_DD, p_dinvRp, p_dinvRd, p_bd1, p_bp2, p_accp);
    k_spmm<<<D_NUM, 128>>>(p_idxR, p_lenR, CAP_PP, p_dinvRd, p_dinvRp, p_bp1, p_bd1, nullptr);
    k_spmm<<<P_NUM, 128>>>(p_idxRT, p_curRT, CAP_DD, p_dinvRp, p_dinvRd, p_bd1, p_bp1, p_accp);
    k_scale<<<(PB + 255) / 256, 256>>>(p_pro_int, p_accp, 0.25f, PB);

    // ---- phase G: attention heads + log_softmax
    k_att<<<D_NUM, 128>>>(p_dru_int, WA_drug, BA_drug, HA_drug, p_wdrug);
    k_logsoftmax<<<1, 1024>>>(p_wdrug, D_NUM);
    k_att<<<P_NUM, 128>>>(p_pro_int, WA_pro, BA_pro, HA_pro, p_wpro);
    k_logsoftmax<<<1, 1024>>>(p_wpro, P_NUM);
    k_att<<<D_NUM, 128>>>(p_emb2, WB_drug, BB_drug, HB_drug, p_wdrel);
    k_logsoftmax<<<1, 1024>>>(p_wdrel, D_NUM);
    k_att<<<P_NUM, 128>>>(p_emb3, WB_pro, BB_pro, HB_pro, p_wprel);
    k_logsoftmax<<<1, 1024>>>(p_wprel, P_NUM);
    k_att<<<D_NUM, 128>>>(p_emb4, WA_sim, BA_sim, HA_sim, p_wdsim);
    k_logsoftmax<<<1, 1024>>>(p_wdsim, D_NUM);

    // ---- phase H: weighted combine
    k_comb_dru<<<(DB + 255) / 256, 256>>>();
    k_comb_pro<<<(PB + 255) / 256, 256>>>();

    // ---- phase I: final score GEMM + standardize + sigmoid
    dim3 fg((P_NUM + 63) / 64, (D_NUM + 63) / 64);
    k_final_gemm<<<fg, 256>>>();
    k_finalize<<<4096, 256>>>(out);
}

// round 2
// speedup vs baseline: 1.1863x; 1.1863x over previous
#include <cuda_runtime.h>
#include <math.h>
#include <stdint.h>

#define D_NUM 1500
#define P_NUM 4500
#define NTOT  6000
#define EMB   128
#define CAP_DD 64    // ELL width, 1500-col domain (mean nnz ~7.5)
#define CAP_PP 128   // ELL width, 4500-col domain (mean nnz ~22.5)
#define DB (D_NUM*EMB)
#define PB (P_NUM*EMB)

// ---------------- scratch (static __device__, no allocs) ----------------
__device__ int g_idx2[D_NUM*CAP_DD]; __device__ int g_len2[D_NUM];
__device__ int g_idx4[D_NUM*CAP_DD]; __device__ int g_len4[D_NUM];
__device__ int g_idx3[P_NUM*CAP_PP]; __device__ int g_len3[P_NUM];
__device__ int g_idxR[D_NUM*CAP_PP]; __device__ int g_lenR[D_NUM];
__device__ int g_idxRT[P_NUM*CAP_DD]; __device__ int g_curRT[P_NUM];

__device__ float g_dinv2[D_NUM], g_cinv2[D_NUM];
__device__ float g_dinv3[P_NUM], g_cinv3[P_NUM];
__device__ float g_dinv4[D_NUM];
__device__ float g_dinvRd[D_NUM], g_cinvRd[D_NUM];
__device__ float g_dinvRp[P_NUM], g_cinvRp[P_NUM];

__device__ float g_dru_str[DB], g_pro_str[PB];
__device__ float g_nei2[DB],    g_nei3[PB];
__device__ float g_emb2[DB],    g_emb3[PB],  g_emb4[DB];
__device__ float g_cur[PB],     g_nxt[PB],   g_acc[PB];
__device__ float g_temd[DB],    g_temp[PB];
__device__ float g_one_emb[DB], g_two_all[PB], g_one_all[DB], g_two_emb[PB];
__device__ float g_bd1[DB],     g_bp1[PB],   g_bp2[PB];
__device__ float g_accd[DB],    g_accp[PB];
__device__ float g_dru_int[DB], g_pro_int[PB];
__device__ float g_tmpp[PB],    g_Wc[EMB*EMB];
__device__ float g_fin_d[DB],   g_fin_p[PB];
__device__ float g_wdrug[D_NUM], g_wdrel[D_NUM], g_wdsim[D_NUM];
__device__ float g_wpro[P_NUM],  g_wprel[P_NUM];
__device__ float g_y[(size_t)D_NUM*P_NUM];
__device__ double g_stats[2];

// ---------------- kernels ----------------

// Vectorized one-pass extraction: float4 coalesced reads, shared-atomic
// collection, then an insertion sort restores deterministic column order.
__global__ void k_ell_fill(const float* __restrict__ base, int row0, int col0,
                           int ncols, int cap, int* __restrict__ idx,
                           int* __restrict__ len) {
    int r = blockIdx.x;
    const float4* row4 = (const float4*)(base + (size_t)(row0 + r) * NTOT + col0);
    int nv = ncols >> 2;   // ncols divisible by 4 for all call sites
    __shared__ int cnt;
    __shared__ int buf[128];
    if (threadIdx.x == 0) cnt = 0;
    __syncthreads();
    for (int i = threadIdx.x; i < nv; i += blockDim.x) {
        float4 v = __ldg(&row4[i]);
        int c = i << 2;
        if (v.x == 1.0f) { int p = atomicAdd(&cnt, 1); if (p < 128) buf[p] = c; }
        if (v.y == 1.0f) { int p = atomicAdd(&cnt, 1); if (p < 128) buf[p] = c + 1; }
        if (v.z == 1.0f) { int p = atomicAdd(&cnt, 1); if (p < 128) buf[p] = c + 2; }
        if (v.w == 1.0f) { int p = atomicAdd(&cnt, 1); if (p < 128) buf[p] = c + 3; }
    }
    __syncthreads();
    int L = min(cnt, cap);
    if (threadIdx.x == 0) {
        len[r] = L;
        for (int i = 1; i < L; i++) {           // deterministic order
            int v = buf[i]; int j = i - 1;
            while (j >= 0 && buf[j] > v) { buf[j + 1] = buf[j]; j--; }
            buf[j + 1] = v;
        }
    }
    __syncthreads();
    for (int i = threadIdx.x; i < L; i += blockDim.x)
        idx[(size_t)r * cap + i] = buf[i];
}

// Build ELL of R^T from ELL of R (atomics, then sorted for determinism).
__global__ void k_rt_fill() {
    int r = blockIdx.x;
    int L = g_lenR[r];
    for (int p = threadIdx.x; p < L; p += blockDim.x) {
        int c = g_idxR[r * CAP_PP + p];
        int pos = atomicAdd(&g_curRT[c], 1);
        if (pos < CAP_DD) g_idxRT[c * CAP_DD + pos] = r;
    }
}
__global__ void k_rt_sort() {
    int c = blockIdx.x * blockDim.x + threadIdx.x;
    if (c >= P_NUM) return;
    int L = min(g_curRT[c], CAP_DD);
    g_curRT[c] = L;
    int* a = &g_idxRT[c * CAP_DD];
    for (int i = 1; i < L; i++) {
        int v = a[i]; int j = i - 1;
        while (j >= 0 && a[j] > v) { a[j + 1] = a[j]; j--; }
        a[j + 1] = v;
    }
}

// All degree scales in one launch.
__global__ void k_scales_all() {
    int i = blockIdx.x * blockDim.x + threadIdx.x;
    if (i < D_NUM) {
        int d;
        d = g_len2[i]; g_dinv2[i] = d > 0 ? rsqrtf((float)d) : 0.0f;
                       g_cinv2[i] = d > 0 ? 1.0f / (float)d : 0.0f;
        d = g_len4[i]; g_dinv4[i] = d > 0 ? rsqrtf((float)d) : 0.0f;
        d = g_lenR[i]; g_dinvRd[i] = d > 0 ? rsqrtf((float)d) : 0.0f;
                       g_cinvRd[i] = d > 0 ? 1.0f / (float)d : 0.0f;
    }
    if (i < P_NUM) {
        int d;
        d = g_len3[i]; g_dinv3[i] = d > 0 ? rsqrtf((float)d) : 0.0f;
                       g_cinv3[i] = d > 0 ? 1.0f / (float)d : 0.0f;
        d = g_curRT[i]; g_dinvRp[i] = d > 0 ? rsqrtf((float)d) : 0.0f;
                        g_cinvRp[i] = d > 0 ? 1.0f / (float)d : 0.0f;
    }
}

// C(n x 128) = A(n x k) @ W(k x 128) [+ bias]; optional duplicate output C2.
// 16 rows per block, 128 threads (one output column each).
__global__ void k_gemm128(const float* __restrict__ A, int n, int k,
                          const float* __restrict__ W, const float* __restrict__ bias,
                          float* __restrict__ C, float* __restrict__ C2) {
    __shared__ float sA[16 * 512];
    int r0 = blockIdx.x * 16;
    for (int i = threadIdx.x; i < 16 * k; i += 128) {
        int rr = i / k, kk = i - rr * k;
        int gr = r0 + rr;
        sA[rr * k + kk] = (gr < n) ? __ldg(&A[(size_t)gr * k + kk]) : 0.0f;
    }
    __syncthreads();
    int c = threadIdx.x;
    float acc[16];
#pragma unroll
    for (int rr = 0; rr < 16; rr++) acc[rr] = 0.0f;
    for (int kk = 0; kk < k; kk++) {
        float w = __ldg(&W[(size_t)kk * EMB + c]);
#pragma unroll
        for (int rr = 0; rr < 16; rr++) acc[rr] += sA[rr * k + kk] * w;
    }
    float b = bias ? bias[c] : 0.0f;
#pragma unroll
    for (int rr = 0; rr < 16; rr++) {
        int gr = r0 + rr;
        if (gr < n) {
            float v = acc[rr] + b;
            C[(size_t)gr * EMB + c] = v;
            if (C2) C2[(size_t)gr * EMB + c] = v;
        }
    }
}

// out[r,:] = rs[r] * sum_{j in row r} (cs?cs[j]:1) * x[j,:]
// optional acc +=, optional fin = (acc+s)*fscale on the final layer.
// Indices/factors staged in smem; gather loop unrolled x4 for MLP.
__global__ void k_spmm(const int* __restrict__ idx, const int* __restrict__ len,
                       int cap, const float* __restrict__ rs,
                       const float* __restrict__ cs, const float* __restrict__ x,
                       float* __restrict__ out, float* __restrict__ acc,
                       float* __restrict__ fin, float fscale) {
    int r = blockIdx.x, c = threadIdx.x;
    __shared__ int sj[128];
    __shared__ float sf[128];
    int L = len[r];
    if (c < L) {
        int j = __ldg(&idx[(size_t)r * cap + c]);
        sj[c] = j * EMB;
        sf[c] = cs ? __ldg(cs + j) : 1.0f;
    }
    __syncthreads();
    float s = 0.0f;
    int p = 0;
    for (; p + 4 <= L; p += 4) {
        float v0 = __ldg(&x[(size_t)sj[p] + c]);
        float v1 = __ldg(&x[(size_t)sj[p + 1] + c]);
        float v2 = __ldg(&x[(size_t)sj[p + 2] + c]);
        float v3 = __ldg(&x[(size_t)sj[p + 3] + c]);
        s += sf[p] * v0 + sf[p + 1] * v1 + sf[p + 2] * v2 + sf[p + 3] * v3;
    }
    for (; p < L; p++) s += sf[p] * __ldg(&x[(size_t)sj[p] + c]);
    s *= __ldg(rs + r);
    size_t o = (size_t)r * EMB + c;
    if (out) out[o] = s;
    if (acc) {
        float a = acc[o] + s;
        acc[o] = a;
        if (fin) fin[o] = a * fscale;
    }
}

// one_all = 0.8*dru_str + 0.2*temd ; tmpp = 0.8*pro_str + 0.2*temp  (fused, float4)
__global__ void k_mix() {
    int i = blockIdx.x * blockDim.x + threadIdx.x;
    const int nd = DB / 4;
    const int np = PB / 4;
    if (i < nd) {
        float4 a = ((const float4*)g_dru_str)[i], b = ((const float4*)g_temd)[i];
        float4 o; o.x = 0.8f*a.x+0.2f*b.x; o.y = 0.8f*a.y+0.2f*b.y;
        o.z = 0.8f*a.z+0.2f*b.z; o.w = 0.8f*a.w+0.2f*b.w;
        ((float4*)g_one_all)[i] = o;
    } else if (i < nd + np) {
        int j = i - nd;
        float4 a = ((const float4*)g_pro_str)[j], b = ((const float4*)g_temp)[j];
        float4 o; o.x = 0.8f*a.x+0.2f*b.x; o.y = 0.8f*a.y+0.2f*b.y;
        o.z = 0.8f*a.z+0.2f*b.z; o.w = 0.8f*a.w+0.2f*b.w;
        ((float4*)g_tmpp)[j] = o;
    }
}

// All 5 attention heads in one launch: s[r] = sum_c relu(emb@W + B)[c]*H[c]
__global__ void k_att_all(const float* __restrict__ WA_drug, const float* __restrict__ BA_drug, const float* __restrict__ HA_drug,
                          const float* __restrict__ WA_pro,  const float* __restrict__ BA_pro,  const float* __restrict__ HA_pro,
                          const float* __restrict__ WB_drug, const float* __restrict__ BB_drug, const float* __restrict__ HB_drug,
                          const float* __restrict__ WB_pro,  const float* __restrict__ BB_pro,  const float* __restrict__ HB_pro,
                          const float* __restrict__ WA_sim,  const float* __restrict__ BA_sim,  const float* __restrict__ HA_sim) {
    int head = blockIdx.y;
    const float *emb, *W, *B, *H; float* s; int n;
    switch (head) {
        case 0: emb = g_dru_int; W = WA_drug; B = BA_drug; H = HA_drug; s = g_wdrug; n = D_NUM; break;
        case 1: emb = g_pro_int; W = WA_pro;  B = BA_pro;  H = HA_pro;  s = g_wpro;  n = P_NUM; break;
        case 2: emb = g_emb2;    W = WB_drug; B = BB_drug; H = HB_drug; s = g_wdrel; n = D_NUM; break;
        case 3: emb = g_emb3;    W = WB_pro;  B = BB_pro;  H = HB_pro;  s = g_wprel; n = P_NUM; break;
        default:emb = g_emb4;    W = WA_sim;  B = BA_sim;  H = HA_sim;  s = g_wdsim; n = D_NUM; break;
    }
    int r = blockIdx.x, t = threadIdx.x;
    if (r >= n) return;
    __shared__ float se[EMB];
    se[t] = emb[(size_t)r * EMB + t];
    __syncthreads();
    float d = 0.0f;
#pragma unroll 8
    for (int k = 0; k < EMB; k++) d += se[k] * __ldg(&W[k * EMB + t]);
    float v = fmaxf(d + __ldg(B + t), 0.0f) * __ldg(H + t);
    for (int o = 16; o; o >>= 1) v += __shfl_down_sync(0xffffffffu, v, o);
    __shared__ float sw[4];
    if ((t & 31) == 0) sw[t >> 5] = v;
    __syncthreads();
    if (t == 0) s[r] = sw[0] + sw[1] + sw[2] + sw[3];
}

// All 5 log-softmax passes in one launch (one block per head).
__global__ void k_ls_all() {
    int head = blockIdx.x;
    float* s; int n;
    switch (head) {
        case 0: s = g_wdrug; n = D_NUM; break;
        case 1: s = g_wpro;  n = P_NUM; break;
        case 2: s = g_wdrel; n = D_NUM; break;
        case 3: s = g_wprel; n = P_NUM; break;
        default:s = g_wdsim; n = D_NUM; break;
    }
    __shared__ float sh[1024];
    int t = threadIdx.x;
    float m = -1e30f;
    for (int i = t; i < n; i += 1024) m = fmaxf(m, s[i]);
    sh[t] = m; __syncthreads();
    for (int o = 512; o; o >>= 1) { if (t < o) sh[t] = fmaxf(sh[t], sh[t + o]); __syncthreads(); }
    float mall = sh[0]; __syncthreads();
    float sum = 0.0f;
    for (int i = t; i < n; i += 1024) sum += expf(s[i] - mall);
    sh[t] = sum; __syncthreads();
    for (int o = 512; o; o >>= 1) { if (t < o) sh[t] += sh[t + o]; __syncthreads(); }
    float lse = mall + logf(sh[0]);
    for (int i = t; i < n; i += 1024) s[i] -= lse;
}

// Fused weighted combine for both drug and protein finals.
__global__ void k_comb() {
    int i = blockIdx.x * blockDim.x + threadIdx.x;
    if (i < DB) {
        int r = i >> 7;
        float wa = g_wdrug[r], wb = g_wdrel[r], wc = g_wdsim[r];
        float a = wa / (wa + wb + wc);
        float b = wb / (a + wb + wc);
        float c = 1.0f - a - b;
        g_fin_d[i] = a * g_dru_int[i] + b * g_emb2[i] + c * g_emb4[i];
    } else if (i < DB + PB) {
        int j = i - DB;
        int r = j >> 7;
        float wa = g_wpro[r], wb = g_wprel[r];
        float pa = wa / (wa + wb);
        g_fin_p[j] = pa * g_pro_int[j] + (1.0f - pa) * g_emb3[j];
    }
}

// Y = fin_d @ fin_p^T, 128x128 tile, 8x8/thread, fused fp64 sum/sumsq.
__global__ void __launch_bounds__(256) k_final_gemm() {
    __shared__ float As[128][33];
    __shared__ float Bs[128][33];
    int bi = blockIdx.y * 128, bj = blockIdx.x * 128;
    int t = threadIdx.x;
    int tx = t & 15, ty = t >> 4;
    int m0 = ty * 8, n0 = tx * 8;
    float acc[8][8];
#pragma unroll
    for (int i = 0; i < 8; i++)
#pragma unroll
        for (int j = 0; j < 8; j++) acc[i][j] = 0.0f;
    for (int k0 = 0; k0 < EMB; k0 += 32) {
#pragma unroll
        for (int it = 0; it < 16; it++) {
            int e = t + it * 256;
            int rr = e >> 5, kk = e & 31;
            int gi = bi + rr, gj = bj + rr;
            As[rr][kk] = (gi < D_NUM) ? g_fin_d[(size_t)gi * EMB + k0 + kk] : 0.0f;
            Bs[rr][kk] = (gj < P_NUM) ? g_fin_p[(size_t)gj * EMB + k0 + kk] : 0.0f;
        }
        __syncthreads();
#pragma unroll
        for (int kk = 0; kk < 32; kk++) {
            float ra[8], rb[8];
#pragma unroll
            for (int i = 0; i < 8; i++) ra[i] = As[m0 + i][kk];
#pragma unroll
            for (int j = 0; j < 8; j++) rb[j] = Bs[n0 + j][kk];
#pragma unroll
            for (int i = 0; i < 8; i++)
#pragma unroll
                for (int j = 0; j < 8; j++) acc[i][j] += ra[i] * rb[j];
        }
        __syncthreads();
    }
    double ls = 0.0, lq = 0.0;
#pragma unroll
    for (int i = 0; i < 8; i++) {
        int gi = bi + m0 + i;
        if (gi < D_NUM) {
#pragma unroll
            for (int j = 0; j < 8; j++) {
                int gj = bj + n0 + j;
                if (gj < P_NUM) {
                    float v = acc[i][j];
                    g_y[(size_t)gi * P_NUM + gj] = v;
                    ls += v;
                    lq += (double)v * v;
                }
            }
        }
    }
    __shared__ double sd[256];
    sd[t] = ls; __syncthreads();
    for (int o = 128; o; o >>= 1) { if (t < o) sd[t] += sd[t + o]; __syncthreads(); }
    if (t == 0) atomicAdd(&g_stats[0], sd[0]);
    __syncthreads();
    sd[t] = lq; __syncthreads();
    for (int o = 128; o; o >>= 1) { if (t < o) sd[t] += sd[t + o]; __syncthreads(); }
    if (t == 0) atomicAdd(&g_stats[1], sd[0]);
}

__global__ void k_finalize(float* __restrict__ out) {
    const double n = (double)D_NUM * (double)P_NUM;
    double sum = g_stats[0], sq = g_stats[1];
    double mean = sum / n;
    double var = (sq - sum * sum / n) / (n - 1.0);
    float istd = (float)(1.0 / sqrt(var));
    float mu = (float)mean;
    const size_t N4 = (size_t)D_NUM * P_NUM / 4;
    const float4* y4 = (const float4*)g_y;
    float4* o4 = (float4*)out;
    for (size_t i = (size_t)blockIdx.x * blockDim.x + threadIdx.x; i < N4;
         i += (size_t)gridDim.x * blockDim.x) {
        float4 v = y4[i];
        float4 o;
        o.x = 1.0f / (1.0f + expf(-(v.x - mu) * istd));
        o.y = 1.0f / (1.0f + expf(-(v.y - mu) * istd));
        o.z = 1.0f / (1.0f + expf(-(v.z - mu) * istd));
        o.w = 1.0f / (1.0f + expf(-(v.w - mu) * istd));
        o4[i] = o;
    }
}

// ---------------- host launcher ----------------
extern "C" void kernel_launch(void* const* d_in, const int* in_sizes, int n_in,
                              void* d_out, int out_size) {
    const float* A                 = (const float*)d_in[0];
    const float* drug_structure    = (const float*)d_in[1];
    const float* protein_structure = (const float*)d_in[2];
    const float* lin_drug_w = (const float*)d_in[3];
    const float* lin_drug_b = (const float*)d_in[4];
    const float* lin_pro_w  = (const float*)d_in[5];
    const float* lin_pro_b  = (const float*)d_in[6];
    const float* p_weight   = (const float*)d_in[7];
    const float* d_weight_i = (const float*)d_in[8];
    const float* pd_weight_p = (const float*)d_in[9];
    const float* pd_weight_d = (const float*)d_in[10];
    const float* dp_weight_p = (const float*)d_in[11];
    const float* WA_drug = (const float*)d_in[12];
    const float* BA_drug = (const float*)d_in[13];
    const float* HA_drug = (const float*)d_in[14];
    const float* WB_drug = (const float*)d_in[15];
    const float* BB_drug = (const float*)d_in[16];
    const float* HB_drug = (const float*)d_in[17];
    const float* WA_pro = (const float*)d_in[18];
    const float* BA_pro = (const float*)d_in[19];
    const float* HA_pro = (const float*)d_in[20];
    const float* WB_pro = (const float*)d_in[21];
    const float* BB_pro = (const float*)d_in[22];
    const float* HB_pro = (const float*)d_in[23];
    const float* WA_sim = (const float*)d_in[24];
    const float* BA_sim = (const float*)d_in[25];
    const float* HA_sim = (const float*)d_in[26];
    float* out = (float*)d_out;
    (void)in_sizes; (void)n_in; (void)out_size;

    void* tp;
#define SYMI(p, s) cudaGetSymbolAddress(&tp, s); int* p = (int*)tp;
#define SYMF(p, s) cudaGetSymbolAddress(&tp, s); float* p = (float*)tp;
#define SYMD(p, s) cudaGetSymbolAddress(&tp, s); double* p = (double*)tp;
    SYMI(p_idx2, g_idx2)  SYMI(p_len2, g_len2)
    SYMI(p_idx3, g_idx3)  SYMI(p_len3, g_len3)
    SYMI(p_idx4, g_idx4)  SYMI(p_len4, g_len4)
    SYMI(p_idxR, g_idxR)  SYMI(p_lenR, g_lenR)
    SYMI(p_idxRT, g_idxRT) SYMI(p_curRT, g_curRT)
    SYMF(p_dinv2, g_dinv2) SYMF(p_cinv2, g_cinv2)
    SYMF(p_dinv3, g_dinv3) SYMF(p_cinv3, g_cinv3)
    SYMF(p_dinv4, g_dinv4)
    SYMF(p_dinvRd, g_dinvRd) SYMF(p_cinvRd, g_cinvRd)
    SYMF(p_dinvRp, g_dinvRp) SYMF(p_cinvRp, g_cinvRp)
    SYMF(p_dru_str, g_dru_str) SYMF(p_pro_str, g_pro_str)
    SYMF(p_nei2, g_nei2) SYMF(p_nei3, g_nei3)
    SYMF(p_emb2, g_emb2) SYMF(p_emb3, g_emb3) SYMF(p_emb4, g_emb4)
    SYMF(p_cur, g_cur) SYMF(p_nxt, g_nxt) SYMF(p_acc, g_acc)
    SYMF(p_temd, g_temd) SYMF(p_temp, g_temp)
    SYMF(p_one_emb, g_one_emb) SYMF(p_two_all, g_two_all)
    SYMF(p_one_all, g_one_all) SYMF(p_two_emb, g_two_emb)
    SYMF(p_bd1, g_bd1) SYMF(p_bp1, g_bp1) SYMF(p_bp2, g_bp2)
    SYMF(p_accd, g_accd) SYMF(p_accp, g_accp)
    SYMF(p_dru_int, g_dru_int) SYMF(p_pro_int, g_pro_int)
    SYMF(p_tmpp, g_tmpp) SYMF(p_Wc, g_Wc)
    SYMD(p_stats, g_stats)

    const size_t NN = (size_t)NTOT * NTOT;

    // ---- phase A: sparse structure extraction
    k_ell_fill<<<D_NUM, 256>>>(A + 2 * NN, 0, 0, D_NUM, CAP_DD, p_idx2, p_len2);
    k_ell_fill<<<P_NUM, 256>>>(A + 3 * NN, D_NUM, D_NUM, P_NUM, CAP_PP, p_idx3, p_len3);
    k_ell_fill<<<D_NUM, 256>>>(A + 4 * NN, 0, 0, D_NUM, CAP_DD, p_idx4, p_len4);
    k_ell_fill<<<D_NUM, 256>>>(A, 0, D_NUM, P_NUM, CAP_PP, p_idxR, p_lenR);
    cudaMemsetAsync(p_curRT, 0, P_NUM * sizeof(int), 0);
    cudaMemsetAsync(p_stats, 0, 2 * sizeof(double), 0);
    k_rt_fill<<<D_NUM, 128>>>();
    k_rt_sort<<<(P_NUM + 255) / 256, 256>>>();
    k_scales_all<<<(P_NUM + 255) / 256, 256>>>();

    // ---- phase B: feature lifts
    k_gemm128<<<(D_NUM + 15) / 16, 128>>>(drug_structure, D_NUM, 160, lin_drug_w, lin_drug_b, p_dru_str, nullptr);
    k_gemm128<<<(P_NUM + 15) / 16, 128>>>(protein_structure, P_NUM, 512, lin_pro_w, lin_pro_b, p_pro_str, nullptr);

    // ---- phase C: rel_emb towers (layer = 3); scale fused into last spmm
    // graph 2 (drug relation)
    k_spmm<<<D_NUM, 128>>>(p_idx2, p_len2, CAP_DD, p_cinv2, nullptr, p_dru_str, p_nei2, nullptr, nullptr, 0.f);
    k_gemm128<<<(D_NUM + 15) / 16, 128>>>(p_dru_str, D_NUM, 128, d_weight_i, nullptr, p_cur, p_acc);
    k_spmm<<<D_NUM, 128>>>(p_idx2, p_len2, CAP_DD, p_dinv2, p_dinv2, p_cur, p_nxt, p_acc, nullptr, 0.f);
    k_spmm<<<D_NUM, 128>>>(p_idx2, p_len2, CAP_DD, p_dinv2, p_dinv2, p_nxt, p_cur, p_acc, nullptr, 0.f);
    k_spmm<<<D_NUM, 128>>>(p_idx2, p_len2, CAP_DD, p_dinv2, p_dinv2, p_cur, nullptr, p_acc, p_emb2, 0.25f);
    // graph 3 (protein relation)
    k_spmm<<<P_NUM, 128>>>(p_idx3, p_len3, CAP_PP, p_cinv3, nullptr, p_pro_str, p_nei3, nullptr, nullptr, 0.f);
    k_gemm128<<<(P_NUM + 15) / 16, 128>>>(p_pro_str, P_NUM, 128, p_weight, nullptr, p_cur, p_acc);
    k_spmm<<<P_NUM, 128>>>(p_idx3, p_len3, CAP_PP, p_dinv3, p_dinv3, p_cur, p_nxt, p_acc, nullptr, 0.f);
    k_spmm<<<P_NUM, 128>>>(p_idx3, p_len3, CAP_PP, p_dinv3, p_dinv3, p_nxt, p_cur, p_acc, nullptr, 0.f);
    k_spmm<<<P_NUM, 128>>>(p_idx3, p_len3, CAP_PP, p_dinv3, p_dinv3, p_cur, nullptr, p_acc, p_emb3, 0.25f);
    // graph 4 (drug similarity)
    k_gemm128<<<(D_NUM + 15) / 16, 128>>>(p_dru_str, D_NUM, 128, d_weight_i, nullptr, p_cur, p_acc);
    k_spmm<<<D_NUM, 128>>>(p_idx4, p_len4, CAP_DD, p_dinv4, p_dinv4, p_cur, p_nxt, p_acc, nullptr, 0.f);
    k_spmm<<<D_NUM, 128>>>(p_idx4, p_len4, CAP_DD, p_dinv4, p_dinv4, p_nxt, p_cur, p_acc, nullptr, 0.f);
    k_spmm<<<D_NUM, 128>>>(p_idx4, p_len4, CAP_DD, p_dinv4, p_dinv4, p_cur, nullptr, p_acc, p_emb4, 0.25f);

    // ---- phase D: cross-domain neighbor means
    k_spmm<<<D_NUM, 128>>>(p_idxR, p_lenR, CAP_PP, p_cinvRd, nullptr, p_nei3, p_temd, nullptr, nullptr, 0.f);
    k_spmm<<<P_NUM, 128>>>(p_idxRT, p_curRT, CAP_DD, p_cinvRp, nullptr, p_nei2, p_temp, nullptr, nullptr, 0.f);

    // ---- phase E: mixed features
    k_mix<<<((DB + PB) / 4 + 255) / 256, 256>>>();
    k_gemm128<<<8, 128>>>(dp_weight_p, 128, 128, pd_weight_d, nullptr, p_Wc, nullptr);
    k_gemm128<<<(P_NUM + 15) / 16, 128>>>(p_tmpp, P_NUM, 128, p_Wc, nullptr, p_two_all, nullptr);
    k_gemm128<<<(D_NUM + 15) / 16, 128>>>(p_dru_str, D_NUM, 128, pd_weight_d, nullptr, p_one_emb, p_accd);
    k_gemm128<<<(P_NUM + 15) / 16, 128>>>(p_pro_str, P_NUM, 128, pd_weight_p, nullptr, p_two_emb, p_accp);

    // ---- phase F: bipartite GCNs (scale fused into last spmm of each)
    // dru_int = (x_d + S x_p + S S^T x_d + S S^T S x_p)/4, x_d=one_emb, x_p=two_all
    k_spmm<<<D_NUM, 128>>>(p_idxR, p_lenR, CAP_PP, p_dinvRd, p_dinvRp, p_two_all, p_bd1, p_accd, nullptr, 0.f);
    k_spmm<<<P_NUM, 128>>>(p_idxRT, p_curRT, CAP_DD, p_dinvRp, p_dinvRd, p_one_emb, p_bp1, nullptr, nullptr, 0.f);
    k_spmm<<<P_NUM, 128>>>(p_idxRT, p_curRT, CAP_DD, p_dinvRp, p_dinvRd, p_bd1, p_bp2, nullptr, nullptr, 0.f);
    k_spmm<<<D_NUM, 128>>>(p_idxR, p_lenR, CAP_PP, p_dinvRd, p_dinvRp, p_bp1, nullptr, p_accd, nullptr, 0.f);
    k_spmm<<<D_NUM, 128>>>(p_idxR, p_lenR, CAP_PP, p_dinvRd, p_dinvRp, p_bp2, nullptr, p_accd, p_dru_int, 0.25f);
    // pro_int = (x_p + S^T x_d + S^T S x_p + S^T S S^T x_d)/4, x_d=one_all, x_p=two_emb
    k_spmm<<<P_NUM, 128>>>(p_idxRT, p_curRT, CAP_DD, p_dinvRp, p_dinvRd, p_one_all, p_bp1, p_accp, nullptr, 0.f);
    k_spmm<<<D_NUM, 128>>>(p_idxR, p_lenR, CAP_PP, p_dinvRd, p_dinvRp, p_two_emb, p_bd1, nullptr, nullptr, 0.f);
    k_spmm<<<P_NUM, 128>>>(p_idxRT, p_curRT, CAP_DD, p_dinvRp, p_dinvRd, p_bd1, nullptr, p_accp, nullptr, 0.f);
    k_spmm<<<D_NUM, 128>>>(p_idxR, p_lenR, CAP_PP, p_dinvRd, p_dinvRp, p_bp1, p_bd1, nullptr, nullptr, 0.f);
    k_spmm<<<P_NUM, 128>>>(p_idxRT, p_curRT, CAP_DD, p_dinvRp, p_dinvRd, p_bd1, nullptr, p_accp, p_pro_int, 0.25f);

    // ---- phase G: attention heads + log_softmax (fused)
    dim3 ag(P_NUM, 5);
    k_att_all<<<ag, 128>>>(WA_drug, BA_drug, HA_drug, WA_pro, BA_pro, HA_pro,
                           WB_drug, BB_drug, HB_drug, WB_pro, BB_pro, HB_pro,
                           WA_sim, BA_sim, HA_sim);
    k_ls_all<<<5, 1024>>>();

    // ---- phase H: weighted combine (fused)
    k_comb<<<(DB + PB + 255) / 256, 256>>>();

    // ---- phase I: final score GEMM + standardize + sigmoid
    dim3 fg((P_NUM + 127) / 128, (D_NUM + 127) / 128);
    k_final_gemm<<<fg, 256>>>();
    k_finalize<<<2048, 256>>>(out);
}

// round 3
// speedup vs baseline: 1.3457x; 1.1343x over previous
#include <cuda_runtime.h>
#include <math.h>
#include <stdint.h>

#define D_NUM 1500
#define P_NUM 4500
#define NTOT  6000
#define EMB   128
#define CAP_DD 64
#define CAP_PP 128
#define DB (D_NUM*EMB)
#define PB (P_NUM*EMB)

// ---------------- scratch (static __device__, no allocs) ----------------
__device__ int g_idx2[D_NUM*CAP_DD]; __device__ int g_len2[D_NUM];
__device__ int g_idx4[D_NUM*CAP_DD]; __device__ int g_len4[D_NUM];
__device__ int g_idx3[P_NUM*CAP_PP]; __device__ int g_len3[P_NUM];
__device__ int g_idxR[D_NUM*CAP_PP]; __device__ int g_lenR[D_NUM];
__device__ int g_idxRT[P_NUM*CAP_DD]; __device__ int g_curRT[P_NUM];

__device__ float g_dinv2[D_NUM], g_cinv2[D_NUM];
__device__ float g_dinv3[P_NUM], g_cinv3[P_NUM];
__device__ float g_dinv4[D_NUM];
__device__ float g_dinvRd[D_NUM], g_cinvRd[D_NUM];
__device__ float g_dinvRp[P_NUM], g_cinvRp[P_NUM];

__device__ float g_dru_str[DB], g_pro_str[PB];
__device__ float g_nei2[DB],    g_nei3[PB];
__device__ float g_emb2[DB],    g_emb3[PB],  g_emb4[DB];
__device__ float g_curD[DB],    g_cur3[PB];
__device__ float g_x2a[DB], g_x2b[DB], g_x4a[DB], g_x4b[DB];
__device__ float g_x3a[PB], g_x3b[PB];
__device__ float g_acc2[DB], g_acc3[PB], g_acc4[DB];
__device__ float g_one_emb[DB], g_two_all[PB], g_one_all[DB], g_two_emb[PB];
__device__ float g_bd1[DB],  g_bp1[PB], g_bp2[PB];
__device__ float g_accd[DB], g_accp[PB];
__device__ float g_dru_int[DB], g_pro_int[PB];
__device__ float g_tmpp[PB], g_Wc[EMB*EMB];
__device__ float g_fin_d[DB], g_fin_p[PB];
__device__ float g_wdrug[D_NUM], g_wdrel[D_NUM], g_wdsim[D_NUM];
__device__ float g_wpro[P_NUM],  g_wprel[P_NUM];
__device__ float g_y[(size_t)D_NUM*P_NUM];
__device__ double g_stats[2];

// ---------------- kernels ----------------

// All four ELL extractions in ONE launch (9000 blocks).
__global__ void k_ell_all(const float* __restrict__ A) {
    const size_t NN = (size_t)NTOT * NTOT;
    int b = blockIdx.x;
    const float* base; int r, row0, col0, ncols, cap; int *idx, *len;
    if (b < 1500)      { base = A + 2*NN; r = b;        row0 = 0;     col0 = 0;     ncols = D_NUM; cap = CAP_DD; idx = g_idx2; len = g_len2; }
    else if (b < 6000) { base = A + 3*NN; r = b - 1500; row0 = D_NUM; col0 = D_NUM; ncols = P_NUM; cap = CAP_PP; idx = g_idx3; len = g_len3; }
    else if (b < 7500) { base = A + 4*NN; r = b - 6000; row0 = 0;     col0 = 0;     ncols = D_NUM; cap = CAP_DD; idx = g_idx4; len = g_len4; }
    else               { base = A;        r = b - 7500; row0 = 0;     col0 = D_NUM; ncols = P_NUM; cap = CAP_PP; idx = g_idxR; len = g_lenR; }

    const float4* row4 = (const float4*)(base + (size_t)(row0 + r) * NTOT + col0);
    int nv = ncols >> 2;
    __shared__ int cnt;
    __shared__ int buf[160];
    if (threadIdx.x == 0) cnt = 0;
    __syncthreads();
#pragma unroll 2
    for (int i = threadIdx.x; i < nv; i += blockDim.x) {
        float4 v = __ldg(&row4[i]);
        int c = i << 2;
        if (v.x == 1.0f) { int p = atomicAdd(&cnt, 1); if (p < 160) buf[p] = c; }
        if (v.y == 1.0f) { int p = atomicAdd(&cnt, 1); if (p < 160) buf[p] = c + 1; }
        if (v.z == 1.0f) { int p = atomicAdd(&cnt, 1); if (p < 160) buf[p] = c + 2; }
        if (v.w == 1.0f) { int p = atomicAdd(&cnt, 1); if (p < 160) buf[p] = c + 3; }
    }
    __syncthreads();
    int L = min(cnt, cap);
    if (threadIdx.x == 0) {
        len[r] = L;
        for (int i = 1; i < L; i++) {      // deterministic column order
            int v = buf[i]; int j = i - 1;
            while (j >= 0 && buf[j] > v) { buf[j + 1] = buf[j]; j--; }
            buf[j + 1] = v;
        }
    }
    __syncthreads();
    for (int i = threadIdx.x; i < L; i += blockDim.x)
        idx[(size_t)r * cap + i] = buf[i];
}

__global__ void k_rt_fill() {
    int r = blockIdx.x;
    int L = g_lenR[r];
    for (int p = threadIdx.x; p < L; p += blockDim.x) {
        int c = g_idxR[r * CAP_PP + p];
        int pos = atomicAdd(&g_curRT[c], 1);
        if (pos < CAP_DD) g_idxRT[c * CAP_DD + pos] = r;
    }
}
__global__ void k_rt_sort() {
    int c = blockIdx.x * blockDim.x + threadIdx.x;
    if (c >= P_NUM) return;
    int L = min(g_curRT[c], CAP_DD);
    g_curRT[c] = L;
    int* a = &g_idxRT[c * CAP_DD];
    for (int i = 1; i < L; i++) {
        int v = a[i]; int j = i - 1;
        while (j >= 0 && a[j] > v) { a[j + 1] = a[j]; j--; }
        a[j + 1] = v;
    }
}

__global__ void k_scales_all() {
    int i = blockIdx.x * blockDim.x + threadIdx.x;
    if (i < D_NUM) {
        int d;
        d = g_len2[i]; g_dinv2[i] = d > 0 ? rsqrtf((float)d) : 0.0f;
                       g_cinv2[i] = d > 0 ? 1.0f / (float)d : 0.0f;
        d = g_len4[i]; g_dinv4[i] = d > 0 ? rsqrtf((float)d) : 0.0f;
        d = g_lenR[i]; g_dinvRd[i] = d > 0 ? rsqrtf((float)d) : 0.0f;
                       g_cinvRd[i] = d > 0 ? 1.0f / (float)d : 0.0f;
    }
    if (i < P_NUM) {
        int d;
        d = g_len3[i]; g_dinv3[i] = d > 0 ? rsqrtf((float)d) : 0.0f;
                       g_cinv3[i] = d > 0 ? 1.0f / (float)d : 0.0f;
        d = g_curRT[i]; g_dinvRp[i] = d > 0 ? rsqrtf((float)d) : 0.0f;
                        g_cinvRp[i] = d > 0 ? 1.0f / (float)d : 0.0f;
    }
}

// C(n x 128) = A(n x k) @ W(k x 128) [+bias]; optional duplicates C2, C3.
__global__ void k_gemm128(const float* __restrict__ A, int n, int k,
                          const float* __restrict__ W, const float* __restrict__ bias,
                          float* __restrict__ C, float* __restrict__ C2,
                          float* __restrict__ C3) {
    __shared__ float sA[16 * 512];
    int r0 = blockIdx.x * 16;
    for (int i = threadIdx.x; i < 16 * k; i += 128) {
        int rr = i / k, kk = i - rr * k;
        int gr = r0 + rr;
        sA[rr * k + kk] = (gr < n) ? __ldg(&A[(size_t)gr * k + kk]) : 0.0f;
    }
    __syncthreads();
    int c = threadIdx.x;
    float acc[16];
#pragma unroll
    for (int rr = 0; rr < 16; rr++) acc[rr] = 0.0f;
#pragma unroll 4
    for (int kk = 0; kk < k; kk++) {
        float w = __ldg(&W[(size_t)kk * EMB + c]);
#pragma unroll
        for (int rr = 0; rr < 16; rr++) acc[rr] += sA[rr * k + kk] * w;
    }
    float b = bias ? bias[c] : 0.0f;
#pragma unroll
    for (int rr = 0; rr < 16; rr++) {
        int gr = r0 + rr;
        if (gr < n) {
            float v = acc[rr] + b;
            size_t o = (size_t)gr * EMB + c;
            C[o] = v;
            if (C2) C2[o] = v;
            if (C3) C3[o] = v;
        }
    }
}

// ------------ batched ELL SpMM: up to 4 independent ops per launch ----------
struct SpmmOp {
    const int* idx; const int* len;
    const float* rs; const float* cs; const float* x;
    float* out; float* acc; float* fin;
    const float* mixb; float* mixo;
    int cap; float fscale;
};
struct SpmmBatch { SpmmOp op[4]; int start[5]; int nops; };

__global__ void k_spmm_multi(SpmmBatch b) {
    int blk = blockIdx.x;
    int oi = 0;
    while (oi + 1 < b.nops && blk >= b.start[oi + 1]) oi++;
    SpmmOp o = b.op[oi];
    int r = blk - b.start[oi];
    int c = threadIdx.x;

    __shared__ int sj[128];
    __shared__ float sf[128];
    int L = __ldg(&o.len[r]);
    if (c < L) {
        int j = __ldg(&o.idx[(size_t)r * o.cap + c]);
        sj[c] = j * EMB;
        sf[c] = o.cs ? __ldg(o.cs + j) : 1.0f;
    }
    __syncthreads();
    float s = 0.0f;
    int p = 0;
    for (; p + 4 <= L; p += 4) {
        float v0 = __ldg(&o.x[(size_t)sj[p] + c]);
        float v1 = __ldg(&o.x[(size_t)sj[p + 1] + c]);
        float v2 = __ldg(&o.x[(size_t)sj[p + 2] + c]);
        float v3 = __ldg(&o.x[(size_t)sj[p + 3] + c]);
        s += sf[p] * v0 + sf[p + 1] * v1 + sf[p + 2] * v2 + sf[p + 3] * v3;
    }
    for (; p < L; p++) s += sf[p] * __ldg(&o.x[(size_t)sj[p] + c]);
    s *= __ldg(o.rs + r);
    size_t off = (size_t)r * EMB + c;
    if (o.out) o.out[off] = s;
    if (o.acc) {
        float a = o.acc[off] + s;
        o.acc[off] = a;
        if (o.fin) o.fin[off] = a * o.fscale;
    }
    if (o.mixo) o.mixo[off] = 0.8f * __ldg(&o.mixb[off]) + 0.2f * s;
}

// ------------ attention: tiled GEMM + relu*H + row-reduce, 5 heads batched --
struct AttOp { const float* emb; const float* W; const float* B; const float* H;
               float* s; int n; };
struct AttBatch { AttOp op[5]; int start[6]; };

__global__ void k_att_gemm(AttBatch b) {
    int blk = blockIdx.x;
    int oi = 0;
    while (oi + 1 < 5 && blk >= b.start[oi + 1]) oi++;
    AttOp o = b.op[oi];
    int r0 = (blk - b.start[oi]) * 16;
    int t = threadIdx.x;

    __shared__ float sE[16 * 128];
    for (int i = t; i < 16 * 128; i += 128) {
        int rr = i >> 7, kk = i & 127;
        int gr = r0 + rr;
        sE[i] = (gr < o.n) ? __ldg(&o.emb[(size_t)gr * EMB + kk]) : 0.0f;
    }
    __syncthreads();
    float acc[16];
#pragma unroll
    for (int rr = 0; rr < 16; rr++) acc[rr] = 0.0f;
#pragma unroll 4
    for (int kk = 0; kk < EMB; kk++) {
        float w = __ldg(&o.W[kk * EMB + t]);
#pragma unroll
        for (int rr = 0; rr < 16; rr++) acc[rr] += sE[rr * 128 + kk] * w;
    }
    float bb = __ldg(o.B + t), hh = __ldg(o.H + t);
    __syncthreads();
#pragma unroll
    for (int rr = 0; rr < 16; rr++)
        sE[rr * 128 + t] = fmaxf(acc[rr] + bb, 0.0f) * hh;
    __syncthreads();
    int w = t >> 5, lane = t & 31;
#pragma unroll
    for (int i = 0; i < 4; i++) {
        int row = w * 4 + i;
        float v = sE[row * 128 + lane] + sE[row * 128 + lane + 32]
                + sE[row * 128 + lane + 64] + sE[row * 128 + lane + 96];
        for (int off = 16; off; off >>= 1) v += __shfl_down_sync(0xffffffffu, v, off);
        if (lane == 0 && r0 + row < o.n) o.s[r0 + row] = v;
    }
}

__global__ void k_ls_all() {
    int head = blockIdx.x;
    float* s; int n;
    switch (head) {
        case 0: s = g_wdrug; n = D_NUM; break;
        case 1: s = g_wpro;  n = P_NUM; break;
        case 2: s = g_wdrel; n = D_NUM; break;
        case 3: s = g_wprel; n = P_NUM; break;
        default:s = g_wdsim; n = D_NUM; break;
    }
    __shared__ float sh[1024];
    int t = threadIdx.x;
    float m = -1e30f;
    for (int i = t; i < n; i += 1024) m = fmaxf(m, s[i]);
    sh[t] = m; __syncthreads();
    for (int o = 512; o; o >>= 1) { if (t < o) sh[t] = fmaxf(sh[t], sh[t + o]); __syncthreads(); }
    float mall = sh[0]; __syncthreads();
    float sum = 0.0f;
    for (int i = t; i < n; i += 1024) sum += expf(s[i] - mall);
    sh[t] = sum; __syncthreads();
    for (int o = 512; o; o >>= 1) { if (t < o) sh[t] += sh[t + o]; __syncthreads(); }
    float lse = mall + logf(sh[0]);
    for (int i = t; i < n; i += 1024) s[i] -= lse;
}

__global__ void k_comb() {
    int i = blockIdx.x * blockDim.x + threadIdx.x;
    if (i < DB) {
        int r = i >> 7;
        float wa = g_wdrug[r], wb = g_wdrel[r], wc = g_wdsim[r];
        float a = wa / (wa + wb + wc);
        float b = wb / (a + wb + wc);
        float c = 1.0f - a - b;
        g_fin_d[i] = a * g_dru_int[i] + b * g_emb2[i] + c * g_emb4[i];
    } else if (i < DB + PB) {
        int j = i - DB;
        int r = j >> 7;
        float wa = g_wpro[r], wb = g_wprel[r];
        float pa = wa / (wa + wb);
        g_fin_p[j] = pa * g_pro_int[j] + (1.0f - pa) * g_emb3[j];
    }
}

// Y = fin_d @ fin_p^T, 128x128 tile, 8x8/thread, k-major smem, float4 LDS,
// fused fp64 sum/sumsq.
__global__ void __launch_bounds__(256) k_final_gemm() {
    __shared__ __align__(16) float sA[32 * 132];
    __shared__ __align__(16) float sB[32 * 132];
    int bi = blockIdx.y * 128, bj = blockIdx.x * 128;
    int t = threadIdx.x;
    int tx = t & 15, ty = t >> 4;
    int m0 = ty * 8, n0 = tx * 8;
    float acc[8][8];
#pragma unroll
    for (int i = 0; i < 8; i++)
#pragma unroll
        for (int j = 0; j < 8; j++) acc[i][j] = 0.0f;

    for (int k0 = 0; k0 < EMB; k0 += 32) {
#pragma unroll
        for (int it = 0; it < 4; it++) {
            int e = t + it * 256;          // 0..1023
            int rr = e >> 3, kv = e & 7;   // row, k-float4
            int gi = bi + rr, gj = bj + rr;
            float4 va = (gi < D_NUM) ? *(const float4*)&g_fin_d[(size_t)gi * EMB + k0 + kv * 4]
                                     : make_float4(0.f, 0.f, 0.f, 0.f);
            float4 vb = (gj < P_NUM) ? *(const float4*)&g_fin_p[(size_t)gj * EMB + k0 + kv * 4]
                                     : make_float4(0.f, 0.f, 0.f, 0.f);
            sA[(kv * 4 + 0) * 132 + rr] = va.x;
            sA[(kv * 4 + 1) * 132 + rr] = va.y;
            sA[(kv * 4 + 2) * 132 + rr] = va.z;
            sA[(kv * 4 + 3) * 132 + rr] = va.w;
            sB[(kv * 4 + 0) * 132 + rr] = vb.x;
            sB[(kv * 4 + 1) * 132 + rr] = vb.y;
            sB[(kv * 4 + 2) * 132 + rr] = vb.z;
            sB[(kv * 4 + 3) * 132 + rr] = vb.w;
        }
        __syncthreads();
#pragma unroll
        for (int kk = 0; kk < 32; kk++) {
            const float* pa = &sA[kk * 132 + m0];
            const float* pb = &sB[kk * 132 + n0];
            float4 a0 = *(const float4*)pa;
            float4 a1 = *(const float4*)(pa + 4);
            float4 b0 = *(const float4*)pb;
            float4 b1 = *(const float4*)(pb + 4);
            float ra[8] = {a0.x, a0.y, a0.z, a0.w, a1.x, a1.y, a1.z, a1.w};
            float rb[8] = {b0.x, b0.y, b0.z, b0.w, b1.x, b1.y, b1.z, b1.w};
#pragma unroll
            for (int i = 0; i < 8; i++)
#pragma unroll
                for (int j = 0; j < 8; j++) acc[i][j] += ra[i] * rb[j];
        }
        __syncthreads();
    }
    double ls = 0.0, lq = 0.0;
#pragma unroll
    for (int i = 0; i < 8; i++) {
        int gi = bi + m0 + i;
        if (gi < D_NUM) {
#pragma unroll
            for (int j = 0; j < 8; j++) {
                int gj = bj + n0 + j;
                if (gj < P_NUM) {
                    float v = acc[i][j];
                    g_y[(size_t)gi * P_NUM + gj] = v;
                    ls += v;
                    lq += (double)v * v;
                }
            }
        }
    }
    __shared__ double sd[256];
    sd[t] = ls; __syncthreads();
    for (int o = 128; o; o >>= 1) { if (t < o) sd[t] += sd[t + o]; __syncthreads(); }
    if (t == 0) atomicAdd(&g_stats[0], sd[0]);
    __syncthreads();
    sd[t] = lq; __syncthreads();
    for (int o = 128; o; o >>= 1) { if (t < o) sd[t] += sd[t + o]; __syncthreads(); }
    if (t == 0) atomicAdd(&g_stats[1], sd[0]);
}

__global__ void k_finalize(float* __restrict__ out) {
    const double n = (double)D_NUM * (double)P_NUM;
    double sum = g_stats[0], sq = g_stats[1];
    double mean = sum / n;
    double var = (sq - sum * sum / n) / (n - 1.0);
    float istd = (float)(1.0 / sqrt(var));
    float mu = (float)mean;
    const size_t N4 = (size_t)D_NUM * P_NUM / 4;
    const float4* y4 = (const float4*)g_y;
    float4* o4 = (float4*)out;
    for (size_t i = (size_t)blockIdx.x * blockDim.x + threadIdx.x; i < N4;
         i += (size_t)gridDim.x * blockDim.x) {
        float4 v = y4[i];
        float4 o;
        o.x = 1.0f / (1.0f + expf(-(v.x - mu) * istd));
        o.y = 1.0f / (1.0f + expf(-(v.y - mu) * istd));
        o.z = 1.0f / (1.0f + expf(-(v.z - mu) * istd));
        o.w = 1.0f / (1.0f + expf(-(v.w - mu) * istd));
        o4[i] = o;
    }
}

// ---------------- host launcher ----------------
extern "C" void kernel_launch(void* const* d_in, const int* in_sizes, int n_in,
                              void* d_out, int out_size) {
    const float* A                 = (const float*)d_in[0];
    const float* drug_structure    = (const float*)d_in[1];
    const float* protein_structure = (const float*)d_in[2];
    const float* lin_drug_w = (const float*)d_in[3];
    const float* lin_drug_b = (const float*)d_in[4];
    const float* lin_pro_w  = (const float*)d_in[5];
    const float* lin_pro_b  = (const float*)d_in[6];
    const float* p_weight   = (const float*)d_in[7];
    const float* d_weight_i = (const float*)d_in[8];
    const float* pd_weight_p = (const float*)d_in[9];
    const float* pd_weight_d = (const float*)d_in[10];
    const float* dp_weight_p = (const float*)d_in[11];
    const float* WA_drug = (const float*)d_in[12];
    const float* BA_drug = (const float*)d_in[13];
    const float* HA_drug = (const float*)d_in[14];
    const float* WB_drug = (const float*)d_in[15];
    const float* BB_drug = (const float*)d_in[16];
    const float* HB_drug = (const float*)d_in[17];
    const float* WA_pro = (const float*)d_in[18];
    const float* BA_pro = (const float*)d_in[19];
    const float* HA_pro = (const float*)d_in[20];
    const float* WB_pro = (const float*)d_in[21];
    const float* BB_pro = (const float*)d_in[22];
    const float* HB_pro = (const float*)d_in[23];
    const float* WA_sim = (const float*)d_in[24];
    const float* BA_sim = (const float*)d_in[25];
    const float* HA_sim = (const float*)d_in[26];
    float* out = (float*)d_out;
    (void)in_sizes; (void)n_in; (void)out_size;

    void* tp;
#define SYMI(p, s) cudaGetSymbolAddress(&tp, s); int* p = (int*)tp;
#define SYMF(p, s) cudaGetSymbolAddress(&tp, s); float* p = (float*)tp;
#define SYMD(p, s) cudaGetSymbolAddress(&tp, s); double* p = (double*)tp;
    SYMI(p_idx2, g_idx2)  SYMI(p_len2, g_len2)
    SYMI(p_idx3, g_idx3)  SYMI(p_len3, g_len3)
    SYMI(p_idx4, g_idx4)  SYMI(p_len4, g_len4)
    SYMI(p_idxR, g_idxR)  SYMI(p_lenR, g_lenR)
    SYMI(p_idxRT, g_idxRT) SYMI(p_curRT, g_curRT)
    SYMF(p_dinv2, g_dinv2) SYMF(p_cinv2, g_cinv2)
    SYMF(p_dinv3, g_dinv3) SYMF(p_cinv3, g_cinv3)
    SYMF(p_dinv4, g_dinv4)
    SYMF(p_dinvRd, g_dinvRd) SYMF(p_cinvRd, g_cinvRd)
    SYMF(p_dinvRp, g_dinvRp) SYMF(p_cinvRp, g_cinvRp)
    SYMF(p_dru_str, g_dru_str) SYMF(p_pro_str, g_pro_str)
    SYMF(p_nei2, g_nei2) SYMF(p_nei3, g_nei3)
    SYMF(p_emb2, g_emb2) SYMF(p_emb3, g_emb3) SYMF(p_emb4, g_emb4)
    SYMF(p_curD, g_curD) SYMF(p_cur3, g_cur3)
    SYMF(p_x2a, g_x2a) SYMF(p_x2b, g_x2b)
    SYMF(p_x4a, g_x4a) SYMF(p_x4b, g_x4b)
    SYMF(p_x3a, g_x3a) SYMF(p_x3b, g_x3b)
    SYMF(p_acc2, g_acc2) SYMF(p_acc3, g_acc3) SYMF(p_acc4, g_acc4)
    SYMF(p_one_emb, g_one_emb) SYMF(p_two_all, g_two_all)
    SYMF(p_one_all, g_one_all) SYMF(p_two_emb, g_two_emb)
    SYMF(p_bd1, g_bd1) SYMF(p_bp1, g_bp1) SYMF(p_bp2, g_bp2)
    SYMF(p_accd, g_accd) SYMF(p_accp, g_accp)
    SYMF(p_dru_int, g_dru_int) SYMF(p_pro_int, g_pro_int)
    SYMF(p_tmpp, g_tmpp) SYMF(p_Wc, g_Wc)
    SYMF(p_dru_int2, g_dru_int) // alias unused
    SYMF(p_wdrug, g_wdrug) SYMF(p_wdrel, g_wdrel) SYMF(p_wdsim, g_wdsim)
    SYMF(p_wpro, g_wpro) SYMF(p_wprel, g_wprel)
    SYMD(p_stats, g_stats)

    // ---- phase A: sparse extraction (single launch) + transpose + scales
    k_ell_all<<<9000, 256>>>(A);
    cudaMemsetAsync(p_curRT, 0, P_NUM * sizeof(int), 0);
    cudaMemsetAsync(p_stats, 0, 2 * sizeof(double), 0);
    k_rt_fill<<<D_NUM, 128>>>();
    k_rt_sort<<<(P_NUM + 255) / 256, 256>>>();
    k_scales_all<<<(P_NUM + 255) / 256, 256>>>();

    // ---- phase B: feature lifts
    k_gemm128<<<(D_NUM + 15) / 16, 128>>>(drug_structure, D_NUM, 160, lin_drug_w, lin_drug_b, p_dru_str, nullptr, nullptr);
    k_gemm128<<<(P_NUM + 15) / 16, 128>>>(protein_structure, P_NUM, 512, lin_pro_w, lin_pro_b, p_pro_str, nullptr, nullptr);

    SpmmBatch B;

    // ---- neighbor means (graphs 2 & 3) in one launch
    B.nops = 2;
    B.op[0] = {p_idx2, p_len2, p_cinv2, nullptr, p_dru_str, p_nei2, nullptr, nullptr, nullptr, nullptr, CAP_DD, 0.f};
    B.op[1] = {p_idx3, p_len3, p_cinv3, nullptr, p_pro_str, p_nei3, nullptr, nullptr, nullptr, nullptr, CAP_PP, 0.f};
    B.start[0] = 0; B.start[1] = D_NUM; B.start[2] = D_NUM + P_NUM;
    k_spmm_multi<<<D_NUM + P_NUM, 128>>>(B);

    // ---- tower inputs: graphs 2 & 4 share dru_str @ d_weight_i
    k_gemm128<<<(D_NUM + 15) / 16, 128>>>(p_dru_str, D_NUM, 128, d_weight_i, nullptr, p_curD, p_acc2, p_acc4);
    k_gemm128<<<(P_NUM + 15) / 16, 128>>>(p_pro_str, P_NUM, 128, p_weight, nullptr, p_cur3, p_acc3, nullptr);

    // ---- GCN towers, 3 layers, all graphs per launch
    B.nops = 3;
    B.start[0] = 0; B.start[1] = D_NUM; B.start[2] = D_NUM + P_NUM; B.start[3] = 2 * D_NUM + P_NUM;
    // layer 1
    B.op[0] = {p_idx2, p_len2, p_dinv2, p_dinv2, p_curD, p_x2a, p_acc2, nullptr, nullptr, nullptr, CAP_DD, 0.f};
    B.op[1] = {p_idx3, p_len3, p_dinv3, p_dinv3, p_cur3, p_x3a, p_acc3, nullptr, nullptr, nullptr, CAP_PP, 0.f};
    B.op[2] = {p_idx4, p_len4, p_dinv4, p_dinv4, p_curD, p_x4a, p_acc4, nullptr, nullptr, nullptr, CAP_DD, 0.f};
    k_spmm_multi<<<2 * D_NUM + P_NUM, 128>>>(B);
    // layer 2
    B.op[0].x = p_x2a; B.op[0].out = p_x2b;
    B.op[1].x = p_x3a; B.op[1].out = p_x3b;
    B.op[2].x = p_x4a; B.op[2].out = p_x4b;
    k_spmm_multi<<<2 * D_NUM + P_NUM, 128>>>(B);
    // layer 3 (+ finalize /4)
    B.op[0] = {p_idx2, p_len2, p_dinv2, p_dinv2, p_x2b, nullptr, p_acc2, p_emb2, nullptr, nullptr, CAP_DD, 0.25f};
    B.op[1] = {p_idx3, p_len3, p_dinv3, p_dinv3, p_x3b, nullptr, p_acc3, p_emb3, nullptr, nullptr, CAP_PP, 0.25f};
    B.op[2] = {p_idx4, p_len4, p_dinv4, p_dinv4, p_x4b, nullptr, p_acc4, p_emb4, nullptr, nullptr, CAP_DD, 0.25f};
    k_spmm_multi<<<2 * D_NUM + P_NUM, 128>>>(B);

    // ---- cross-domain neighbor means with fused 0.8/0.2 mix
    B.nops = 2;
    B.op[0] = {p_idxR, p_lenR, p_cinvRd, nullptr, p_nei3, nullptr, nullptr, nullptr, p_dru_str, p_one_all, CAP_PP, 0.f};
    B.op[1] = {p_idxRT, p_curRT, p_cinvRp, nullptr, p_nei2, nullptr, nullptr, nullptr, p_pro_str, p_tmpp, CAP_DD, 0.f};
    B.start[0] = 0; B.start[1] = D_NUM; B.start[2] = D_NUM + P_NUM;
    k_spmm_multi<<<D_NUM + P_NUM, 128>>>(B);

    // ---- mixed-feature GEMMs
    k_gemm128<<<8, 128>>>(dp_weight_p, 128, 128, pd_weight_d, nullptr, p_Wc, nullptr, nullptr);
    k_gemm128<<<(P_NUM + 15) / 16, 128>>>(p_tmpp, P_NUM, 128, p_Wc, nullptr, p_two_all, nullptr, nullptr);
    k_gemm128<<<(D_NUM + 15) / 16, 128>>>(p_dru_str, D_NUM, 128, pd_weight_d, nullptr, p_one_emb, p_accd, nullptr);
    k_gemm128<<<(P_NUM + 15) / 16, 128>>>(p_pro_str, P_NUM, 128, pd_weight_p, nullptr, p_two_emb, p_accp, nullptr);

    // ---- bipartite GCNs: 3 fused launches
    // F1: bd1 = S two_all (+accd); bp1 = S^T one_emb; bp1' = S^T one_all (+accp); bd1' = S two_emb
    B.nops = 4;
    B.op[0] = {p_idxR, p_lenR, p_dinvRd, p_dinvRp, p_two_all, p_bd1, p_accd, nullptr, nullptr, nullptr, CAP_PP, 0.f};
    B.op[1] = {p_idxRT, p_curRT, p_dinvRp, p_dinvRd, p_one_emb, p_bp1, nullptr, nullptr, nullptr, nullptr, CAP_DD, 0.f};
    B.op[2] = {p_idxRT, p_curRT, p_dinvRp, p_dinvRd, p_one_all, p_x3a, p_accp, nullptr, nullptr, nullptr, CAP_DD, 0.f};
    B.op[3] = {p_idxR, p_lenR, p_dinvRd, p_dinvRp, p_two_emb, p_x2a, nullptr, nullptr, nullptr, nullptr, CAP_PP, 0.f};
    B.start[0] = 0; B.start[1] = D_NUM; B.start[2] = D_NUM + P_NUM;
    B.start[3] = D_NUM + 2 * P_NUM; B.start[4] = 2 * D_NUM + 2 * P_NUM;
    k_spmm_multi<<<2 * D_NUM + 2 * P_NUM, 128>>>(B);
    // F2: bp2 = S^T bd1; accd += S bp1; accp += S^T bd1'; bd2' = S bp1'
    B.op[0] = {p_idxRT, p_curRT, p_dinvRp, p_dinvRd, p_bd1, p_bp2, nullptr, nullptr, nullptr, nullptr, CAP_DD, 0.f};
    B.op[1] = {p_idxR, p_lenR, p_dinvRd, p_dinvRp, p_bp1, nullptr, p_accd, nullptr, nullptr, nullptr, CAP_PP, 0.f};
    B.op[2] = {p_idxRT, p_curRT, p_dinvRp, p_dinvRd, p_x2a, nullptr, p_accp, nullptr, nullptr, nullptr, CAP_DD, 0.f};
    B.op[3] = {p_idxR, p_lenR, p_dinvRd, p_dinvRp, p_x3a, p_x4a, nullptr, nullptr, nullptr, nullptr, CAP_PP, 0.f};
    B.start[0] = 0; B.start[1] = P_NUM; B.start[2] = P_NUM + D_NUM;
    B.start[3] = 2 * P_NUM + D_NUM; B.start[4] = 2 * P_NUM + 2 * D_NUM;
    k_spmm_multi<<<2 * D_NUM + 2 * P_NUM, 128>>>(B);
    // F3: accd += S bp2 (fin dru_int); accp += S^T bd2' (fin pro_int)
    B.nops = 2;
    B.op[0] = {p_idxR, p_lenR, p_dinvRd, p_dinvRp, p_bp2, nullptr, p_accd, p_dru_int, nullptr, nullptr, CAP_PP, 0.25f};
    B.op[1] = {p_idxRT, p_curRT, p_dinvRp, p_dinvRd, p_x4a, nullptr, p_accp, p_pro_int, nullptr, nullptr, CAP_DD, 0.25f};
    B.start[0] = 0; B.start[1] = D_NUM; B.start[2] = D_NUM + P_NUM;
    k_spmm_multi<<<D_NUM + P_NUM, 128>>>(B);

    // ---- attention heads as tiled GEMMs (one launch) + log-softmax
    AttBatch AB;
    AB.op[0] = {p_dru_int, WA_drug, BA_drug, HA_drug, p_wdrug, D_NUM};
    AB.op[1] = {p_pro_int, WA_pro,  BA_pro,  HA_pro,  p_wpro,  P_NUM};
    AB.op[2] = {p_emb2,    WB_drug, BB_drug, HB_drug, p_wdrel, D_NUM};
    AB.op[3] = {p_emb3,    WB_pro,  BB_pro,  HB_pro,  p_wprel, P_NUM};
    AB.op[4] = {p_emb4,    WA_sim,  BA_sim,  HA_sim,  p_wdsim, D_NUM};
    int db = (D_NUM + 15) / 16, pb = (P_NUM + 15) / 16;
    AB.start[0] = 0;
    AB.start[1] = db;
    AB.start[2] = db + pb;
    AB.start[3] = 2 * db + pb;
    AB.start[4] = 2 * db + 2 * pb;
    AB.start[5] = 3 * db + 2 * pb;
    k_att_gemm<<<AB.start[5], 128>>>(AB);
    k_ls_all<<<5, 1024>>>();

    // ---- combine + final GEMM + standardize/sigmoid
    k_comb<<<(DB + PB + 255) / 256, 256>>>();
    dim3 fg((P_NUM + 127) / 128, (D_NUM + 127) / 128);
    k_final_gemm<<<fg, 256>>>();
    k_finalize<<<2048, 256>>>(out);
}

// round 4
// speedup vs baseline: 1.5082x; 1.1208x over previous
#include <cuda_runtime.h>
#include <math.h>
#include <stdint.h>

#define D_NUM 1500
#define P_NUM 4500
#define NTOT  6000
#define EMB   128
#define CAP_DD 64
#define CAP_PP 128
#define DB (D_NUM*EMB)
#define PB (P_NUM*EMB)
#define MEGA_BLKS 296
#define MEGA_THREADS 256

// ---------------- scratch (static __device__, no allocs) ----------------
__device__ __align__(128) int g_idx2[D_NUM*CAP_DD]; __device__ int g_len2[D_NUM];
__device__ __align__(128) int g_idx4[D_NUM*CAP_DD]; __device__ int g_len4[D_NUM];
__device__ __align__(128) int g_idx3[P_NUM*CAP_PP]; __device__ int g_len3[P_NUM];
__device__ __align__(128) int g_idxR[D_NUM*CAP_PP]; __device__ int g_lenR[D_NUM];
__device__ __align__(128) int g_idxRT[P_NUM*CAP_DD]; __device__ int g_curRT[P_NUM];

__device__ float g_dinv2[D_NUM], g_cinv2[D_NUM];
__device__ float g_dinv3[P_NUM], g_cinv3[P_NUM];
__device__ float g_dinv4[D_NUM];
__device__ float g_dinvRd[D_NUM], g_cinvRd[D_NUM];
__device__ float g_dinvRp[P_NUM], g_cinvRp[P_NUM];

__device__ __align__(128) float g_dru_str[DB], g_pro_str[PB];
__device__ __align__(128) float g_nei2[DB],    g_nei3[PB];
__device__ __align__(128) float g_emb2[DB],    g_emb3[PB],  g_emb4[DB];
__device__ __align__(128) float g_curD[DB],    g_cur3[PB];
__device__ __align__(128) float g_x2a[DB], g_x2b[DB], g_x4a[DB], g_x4b[DB];
__device__ __align__(128) float g_x3a[PB], g_x3b[PB];
__device__ __align__(128) float g_acc2[DB], g_acc3[PB], g_acc4[DB];
__device__ __align__(128) float g_one_emb[DB], g_two_all[PB], g_one_all[DB], g_two_emb[PB];
__device__ __align__(128) float g_bd1[DB],  g_bp1[PB], g_bp2[PB];
__device__ __align__(128) float g_bdx[DB],  g_bpx[PB], g_bdy[DB];
__device__ __align__(128) float g_accd[DB], g_accp[PB];
__device__ __align__(128) float g_dru_int[DB], g_pro_int[PB];
__device__ __align__(128) float g_tmpp[PB], g_Wc[EMB*EMB];
__device__ __align__(128) float g_fin_d[DB], g_fin_p[PB];
__device__ float g_wdrug[D_NUM], g_wdrel[D_NUM], g_wdsim[D_NUM];
__device__ float g_wpro[P_NUM],  g_wprel[P_NUM];
__device__ __align__(128) float g_y[(size_t)D_NUM*P_NUM];
__device__ double g_stats[2];
__device__ unsigned g_barcnt;

// ---------------- ELL extraction (all four blocks, one launch) -------------
__global__ void k_ell_all(const float* __restrict__ A) {
    const size_t NN = (size_t)NTOT * NTOT;
    int b = blockIdx.x;
    const float* base; int r, row0, col0, ncols, cap; int *idx, *len;
    if (b < 1500)      { base = A + 2*NN; r = b;        row0 = 0;     col0 = 0;     ncols = D_NUM; cap = CAP_DD; idx = g_idx2; len = g_len2; }
    else if (b < 6000) { base = A + 3*NN; r = b - 1500; row0 = D_NUM; col0 = D_NUM; ncols = P_NUM; cap = CAP_PP; idx = g_idx3; len = g_len3; }
    else if (b < 7500) { base = A + 4*NN; r = b - 6000; row0 = 0;     col0 = 0;     ncols = D_NUM; cap = CAP_DD; idx = g_idx4; len = g_len4; }
    else               { base = A;        r = b - 7500; row0 = 0;     col0 = D_NUM; ncols = P_NUM; cap = CAP_PP; idx = g_idxR; len = g_lenR; }

    const float4* row4 = (const float4*)(base + (size_t)(row0 + r) * NTOT + col0);
    int nv = ncols >> 2;
    __shared__ int cnt;
    __shared__ int buf[160];
    if (threadIdx.x == 0) cnt = 0;
    __syncthreads();
#pragma unroll 2
    for (int i = threadIdx.x; i < nv; i += blockDim.x) {
        float4 v = __ldg(&row4[i]);
        int c = i << 2;
        if (v.x == 1.0f) { int p = atomicAdd(&cnt, 1); if (p < 160) buf[p] = c; }
        if (v.y == 1.0f) { int p = atomicAdd(&cnt, 1); if (p < 160) buf[p] = c + 1; }
        if (v.z == 1.0f) { int p = atomicAdd(&cnt, 1); if (p < 160) buf[p] = c + 2; }
        if (v.w == 1.0f) { int p = atomicAdd(&cnt, 1); if (p < 160) buf[p] = c + 3; }
    }
    __syncthreads();
    int L = min(cnt, cap);
    if (threadIdx.x == 0) {
        len[r] = L;
        for (int i = 1; i < L; i++) {      // deterministic column order
            int v = buf[i]; int j = i - 1;
            while (j >= 0 && buf[j] > v) { buf[j + 1] = buf[j]; j--; }
            buf[j + 1] = v;
        }
    }
    __syncthreads();
    for (int i = threadIdx.x; i < L; i += blockDim.x)
        idx[(size_t)r * cap + i] = buf[i];
}

// ---------------- megakernel device helpers ----------------

__device__ __forceinline__ void gsync(unsigned& target) {
    __syncthreads();
    if (threadIdx.x == 0) {
        __threadfence();
        atomicAdd(&g_barcnt, 1u);
        target += gridDim.x;
        unsigned v;
        do {
            asm volatile("ld.acquire.gpu.global.u32 %0, [%1];"
                         : "=r"(v) : "l"(&g_barcnt) : "memory");
        } while (v < target);
    }
    __syncthreads();
}

// C(n x 128) = A(n x k) @ W(k x 128) [+bias], optional dup C2/C3.
// Block processes 16-row tiles strided by gridDim. 256 threads: col x rowhalf.
__device__ void gemm_dev(const float* A, int n, int k,
                         const float* W, bool wext, const float* bias,
                         float* C, float* C2, float* C3, float* sA) {
    int ntiles = (n + 15) >> 4;
    int col = threadIdx.x & 127;
    int half = threadIdx.x >> 7;
    for (int t = blockIdx.x; t < ntiles; t += gridDim.x) {
        int r0 = t << 4;
        __syncthreads();
        for (int i = threadIdx.x; i < (k << 4); i += MEGA_THREADS) {
            int rr = i / k, kk = i - rr * k;
            int gr = r0 + rr;
            sA[rr * k + kk] = (gr < n) ? A[(size_t)gr * k + kk] : 0.0f;
        }
        __syncthreads();
        float acc[8];
#pragma unroll
        for (int rr = 0; rr < 8; rr++) acc[rr] = 0.0f;
        const float* sAr = sA + (half << 3) * k;
        for (int kk = 0; kk < k; kk++) {
            float w = wext ? __ldg(&W[(size_t)kk * EMB + col]) : W[(size_t)kk * EMB + col];
#pragma unroll
            for (int rr = 0; rr < 8; rr++) acc[rr] += sAr[rr * k + kk] * w;
        }
        float b = bias ? __ldg(bias + col) : 0.0f;
#pragma unroll
        for (int rr = 0; rr < 8; rr++) {
            int gr = r0 + (half << 3) + rr;
            if (gr < n) {
                float v = acc[rr] + b;
                size_t o = (size_t)gr * EMB + col;
                C[o] = v;
                if (C2) C2[o] = v;
                if (C3) C3[o] = v;
            }
        }
    }
}

// ELL SpMM: warp per row, lane = one float4 of the 128-wide feature row.
// out[r] = rs[r]*sum_j cs[j]*x[j]; optional acc+=, fin=(acc)*fscale, mix.
__device__ void spmm_dev(const int* idx, const int* len, int cap,
                         const float* rs, const float* cs, const float* x,
                         float* out, float* acc, float* fin, float fscale,
                         const float* mixb, float* mixo, int n) {
    int nw = (gridDim.x * blockDim.x) >> 5;
    int gw = (blockIdx.x * blockDim.x + threadIdx.x) >> 5;
    int lane = threadIdx.x & 31;
    const float4* x4 = (const float4*)x;
    for (int r = gw; r < n; r += nw) {
        int L = len[r];
        float4 s = make_float4(0.f, 0.f, 0.f, 0.f);
        for (int p0 = 0; p0 < L; p0 += 32) {
            int j = 0; float f = 0.f;
            if (p0 + lane < L) {
                j = idx[(size_t)r * cap + p0 + lane];
                f = cs ? cs[j] : 1.0f;
            }
            int m = min(32, L - p0);
            int q = 0;
            for (; q + 4 <= m; q += 4) {
                int j0 = __shfl_sync(0xffffffffu, j, q);
                int j1 = __shfl_sync(0xffffffffu, j, q + 1);
                int j2 = __shfl_sync(0xffffffffu, j, q + 2);
                int j3 = __shfl_sync(0xffffffffu, j, q + 3);
                float f0 = __shfl_sync(0xffffffffu, f, q);
                float f1 = __shfl_sync(0xffffffffu, f, q + 1);
                float f2 = __shfl_sync(0xffffffffu, f, q + 2);
                float f3 = __shfl_sync(0xffffffffu, f, q + 3);
                float4 v0 = x4[(size_t)j0 * 32 + lane];
                float4 v1 = x4[(size_t)j1 * 32 + lane];
                float4 v2 = x4[(size_t)j2 * 32 + lane];
                float4 v3 = x4[(size_t)j3 * 32 + lane];
                s.x += f0 * v0.x + f1 * v1.x + f2 * v2.x + f3 * v3.x;
                s.y += f0 * v0.y + f1 * v1.y + f2 * v2.y + f3 * v3.y;
                s.z += f0 * v0.z + f1 * v1.z + f2 * v2.z + f3 * v3.z;
                s.w += f0 * v0.w + f1 * v1.w + f2 * v2.w + f3 * v3.w;
            }
            for (; q < m; q++) {
                int j0 = __shfl_sync(0xffffffffu, j, q);
                float f0 = __shfl_sync(0xffffffffu, f, q);
                float4 v0 = x4[(size_t)j0 * 32 + lane];
                s.x += f0 * v0.x; s.y += f0 * v0.y;
                s.z += f0 * v0.z; s.w += f0 * v0.w;
            }
        }
        float rr = rs[r];
        s.x *= rr; s.y *= rr; s.z *= rr; s.w *= rr;
        size_t o = (size_t)r * 32 + lane;
        if (out) ((float4*)out)[o] = s;
        if (acc) {
            float4 a = ((const float4*)acc)[o];
            a.x += s.x; a.y += s.y; a.z += s.z; a.w += s.w;
            ((float4*)acc)[o] = a;
            if (fin) {
                float4 ff = make_float4(a.x * fscale, a.y * fscale, a.z * fscale, a.w * fscale);
                ((float4*)fin)[o] = ff;
            }
        }
        if (mixo) {
            float4 mb = ((const float4*)mixb)[o];
            float4 mo = make_float4(0.8f * mb.x + 0.2f * s.x, 0.8f * mb.y + 0.2f * s.y,
                                    0.8f * mb.z + 0.2f * s.z, 0.8f * mb.w + 0.2f * s.w);
            ((float4*)mixo)[o] = mo;
        }
    }
}

// s[r] = sum_c relu(emb[r]@W + B)[c]*H[c]; 16-row tiles.
__device__ void att_dev(const float* emb, const float* W, const float* B,
                        const float* H, float* s, int n, float* sE) {
    int ntiles = (n + 15) >> 4;
    int col = threadIdx.x & 127;
    int half = threadIdx.x >> 7;
    for (int t = blockIdx.x; t < ntiles; t += gridDim.x) {
        int r0 = t << 4;
        __syncthreads();
        for (int i = threadIdx.x; i < 16 * 128; i += MEGA_THREADS) {
            int rr = i >> 7, kk = i & 127;
            int gr = r0 + rr;
            sE[i] = (gr < n) ? emb[(size_t)gr * EMB + kk] : 0.0f;
        }
        __syncthreads();
        float acc[8];
#pragma unroll
        for (int rr = 0; rr < 8; rr++) acc[rr] = 0.0f;
        const float* sEr = sE + (half << 3) * 128;
#pragma unroll 4
        for (int kk = 0; kk < 128; kk++) {
            float w = __ldg(&W[kk * EMB + col]);
#pragma unroll
            for (int rr = 0; rr < 8; rr++) acc[rr] += sEr[rr * 128 + kk] * w;
        }
        float bb = __ldg(B + col), hh = __ldg(H + col);
        __syncthreads();
#pragma unroll
        for (int rr = 0; rr < 8; rr++)
            sE[((half << 3) + rr) * 128 + col] = fmaxf(acc[rr] + bb, 0.0f) * hh;
        __syncthreads();
        int wid = threadIdx.x >> 5, lane = threadIdx.x & 31;
#pragma unroll
        for (int i = 0; i < 2; i++) {
            int row = wid * 2 + i;
            float v = sE[row * 128 + lane] + sE[row * 128 + lane + 32]
                    + sE[row * 128 + lane + 64] + sE[row * 128 + lane + 96];
            for (int off = 16; off; off >>= 1) v += __shfl_down_sync(0xffffffffu, v, off);
            if (lane == 0 && r0 + row < n) s[r0 + row] = v;
        }
    }
}

__device__ void ls_dev(float* s, int n, float* sh) {
    int t = threadIdx.x;
    float m = -1e30f;
    for (int i = t; i < n; i += MEGA_THREADS) m = fmaxf(m, s[i]);
    sh[t] = m; __syncthreads();
    for (int o = 128; o; o >>= 1) { if (t < o) sh[t] = fmaxf(sh[t], sh[t + o]); __syncthreads(); }
    float mall = sh[0]; __syncthreads();
    float sum = 0.0f;
    for (int i = t; i < n; i += MEGA_THREADS) sum += expf(s[i] - mall);
    sh[t] = sum; __syncthreads();
    for (int o = 128; o; o >>= 1) { if (t < o) sh[t] += sh[t + o]; __syncthreads(); }
    float lse = mall + logf(sh[0]);
    __syncthreads();
    for (int i = t; i < n; i += MEGA_THREADS) s[i] -= lse;
}

// ---------------- the megakernel: rt_fill ... combine in ONE launch --------
__global__ void __launch_bounds__(MEGA_THREADS, 2) k_mega(
    const float* __restrict__ drug_structure, const float* __restrict__ protein_structure,
    const float* __restrict__ lin_drug_w, const float* __restrict__ lin_drug_b,
    const float* __restrict__ lin_pro_w, const float* __restrict__ lin_pro_b,
    const float* __restrict__ p_weight, const float* __restrict__ d_weight_i,
    const float* __restrict__ pd_weight_p, const float* __restrict__ pd_weight_d,
    const float* __restrict__ dp_weight_p,
    const float* __restrict__ WA_drug, const float* __restrict__ BA_drug, const float* __restrict__ HA_drug,
    const float* __restrict__ WB_drug, const float* __restrict__ BB_drug, const float* __restrict__ HB_drug,
    const float* __restrict__ WA_pro, const float* __restrict__ BA_pro, const float* __restrict__ HA_pro,
    const float* __restrict__ WB_pro, const float* __restrict__ BB_pro, const float* __restrict__ HB_pro,
    const float* __restrict__ WA_sim, const float* __restrict__ BA_sim, const float* __restrict__ HA_sim) {
    __shared__ float sbuf[16 * 512];
    unsigned target = 0;

    // ---- P1: build R^T (atomics into g_curRT / g_idxRT)
    {
        int nw = (gridDim.x * blockDim.x) >> 5;
        int gw = (blockIdx.x * blockDim.x + threadIdx.x) >> 5;
        int lane = threadIdx.x & 31;
        for (int r = gw; r < D_NUM; r += nw) {
            int L = g_lenR[r];
            for (int p = lane; p < L; p += 32) {
                int c = g_idxR[r * CAP_PP + p];
                int pos = atomicAdd(&g_curRT[c], 1);
                if (pos < CAP_DD) g_idxRT[c * CAP_DD + pos] = r;
            }
        }
    }
    gsync(target);

    // ---- P2: sort R^T rows (determinism) + all degree scales
    {
        int i = blockIdx.x * blockDim.x + threadIdx.x;
        if (i < D_NUM) {
            int d;
            d = g_len2[i]; g_dinv2[i] = d > 0 ? rsqrtf((float)d) : 0.0f;
                           g_cinv2[i] = d > 0 ? 1.0f / (float)d : 0.0f;
            d = g_len4[i]; g_dinv4[i] = d > 0 ? rsqrtf((float)d) : 0.0f;
            d = g_lenR[i]; g_dinvRd[i] = d > 0 ? rsqrtf((float)d) : 0.0f;
                           g_cinvRd[i] = d > 0 ? 1.0f / (float)d : 0.0f;
        }
        if (i < P_NUM) {
            int d = g_len3[i];
            g_dinv3[i] = d > 0 ? rsqrtf((float)d) : 0.0f;
            g_cinv3[i] = d > 0 ? 1.0f / (float)d : 0.0f;
            int L = min(g_curRT[i], CAP_DD);
            g_curRT[i] = L;
            int* a = &g_idxRT[i * CAP_DD];
            for (int q = 1; q < L; q++) {
                int v = a[q]; int jj = q - 1;
                while (jj >= 0 && a[jj] > v) { a[jj + 1] = a[jj]; jj--; }
                a[jj + 1] = v;
            }
            g_dinvRp[i] = L > 0 ? rsqrtf((float)L) : 0.0f;
            g_cinvRp[i] = L > 0 ? 1.0f / (float)L : 0.0f;
        }
    }
    gsync(target);

    // ---- P3: feature lifts + Wc = dp_weight_p @ pd_weight_d
    gemm_dev(drug_structure, D_NUM, 160, lin_drug_w, true, lin_drug_b, g_dru_str, 0, 0, sbuf);
    gemm_dev(protein_structure, P_NUM, 512, lin_pro_w, true, lin_pro_b, g_pro_str, 0, 0, sbuf);
    gemm_dev(dp_weight_p, 128, 128, pd_weight_d, true, 0, g_Wc, 0, 0, sbuf);
    gsync(target);

    // ---- P4: tower-input GEMMs (+acc inits) and neighbor means
    gemm_dev(g_dru_str, D_NUM, 128, d_weight_i, true, 0, g_curD, g_acc2, g_acc4, sbuf);
    gemm_dev(g_pro_str, P_NUM, 128, p_weight, true, 0, g_cur3, g_acc3, 0, sbuf);
    gemm_dev(g_dru_str, D_NUM, 128, pd_weight_d, true, 0, g_one_emb, g_accd, 0, sbuf);
    gemm_dev(g_pro_str, P_NUM, 128, pd_weight_p, true, 0, g_two_emb, g_accp, 0, sbuf);
    spmm_dev(g_idx2, g_len2, CAP_DD, g_cinv2, 0, g_dru_str, g_nei2, 0, 0, 0.f, 0, 0, D_NUM);
    spmm_dev(g_idx3, g_len3, CAP_PP, g_cinv3, 0, g_pro_str, g_nei3, 0, 0, 0.f, 0, 0, P_NUM);
    gsync(target);

    // ---- P5: GCN layer 1 + cross-domain neighbor means with fused mix
    spmm_dev(g_idx2, g_len2, CAP_DD, g_dinv2, g_dinv2, g_curD, g_x2a, g_acc2, 0, 0.f, 0, 0, D_NUM);
    spmm_dev(g_idx3, g_len3, CAP_PP, g_dinv3, g_dinv3, g_cur3, g_x3a, g_acc3, 0, 0.f, 0, 0, P_NUM);
    spmm_dev(g_idx4, g_len4, CAP_DD, g_dinv4, g_dinv4, g_curD, g_x4a, g_acc4, 0, 0.f, 0, 0, D_NUM);
    spmm_dev(g_idxR, g_lenR, CAP_PP, g_cinvRd, 0, g_nei3, 0, 0, 0, 0.f, g_dru_str, g_one_all, D_NUM);
    spmm_dev(g_idxRT, g_curRT, CAP_DD, g_cinvRp, 0, g_nei2, 0, 0, 0, 0.f, g_pro_str, g_tmpp, P_NUM);
    gsync(target);

    // ---- P6: GCN layer 2 + two_all GEMM
    spmm_dev(g_idx2, g_len2, CAP_DD, g_dinv2, g_dinv2, g_x2a, g_x2b, g_acc2, 0, 0.f, 0, 0, D_NUM);
    spmm_dev(g_idx3, g_len3, CAP_PP, g_dinv3, g_dinv3, g_x3a, g_x3b, g_acc3, 0, 0.f, 0, 0, P_NUM);
    spmm_dev(g_idx4, g_len4, CAP_DD, g_dinv4, g_dinv4, g_x4a, g_x4b, g_acc4, 0, 0.f, 0, 0, D_NUM);
    gemm_dev(g_tmpp, P_NUM, 128, g_Wc, false, 0, g_two_all, 0, 0, sbuf);
    gsync(target);

    // ---- P7: GCN layer 3 (finalize towers) + bipartite step 1
    spmm_dev(g_idx2, g_len2, CAP_DD, g_dinv2, g_dinv2, g_x2b, 0, g_acc2, g_emb2, 0.25f, 0, 0, D_NUM);
    spmm_dev(g_idx3, g_len3, CAP_PP, g_dinv3, g_dinv3, g_x3b, 0, g_acc3, g_emb3, 0.25f, 0, 0, P_NUM);
    spmm_dev(g_idx4, g_len4, CAP_DD, g_dinv4, g_dinv4, g_x4b, 0, g_acc4, g_emb4, 0.25f, 0, 0, D_NUM);
    spmm_dev(g_idxR, g_lenR, CAP_PP, g_dinvRd, g_dinvRp, g_two_all, g_bd1, g_accd, 0, 0.f, 0, 0, D_NUM);
    spmm_dev(g_idxRT, g_curRT, CAP_DD, g_dinvRp, g_dinvRd, g_one_emb, g_bp1, 0, 0, 0.f, 0, 0, P_NUM);
    spmm_dev(g_idxRT, g_curRT, CAP_DD, g_dinvRp, g_dinvRd, g_one_all, g_bpx, g_accp, 0, 0.f, 0, 0, P_NUM);
    spmm_dev(g_idxR, g_lenR, CAP_PP, g_dinvRd, g_dinvRp, g_two_emb, g_bdx, 0, 0, 0.f, 0, 0, D_NUM);
    gsync(target);

    // ---- P8: bipartite step 2
    spmm_dev(g_idxRT, g_curRT, CAP_DD, g_dinvRp, g_dinvRd, g_bd1, g_bp2, 0, 0, 0.f, 0, 0, P_NUM);
    spmm_dev(g_idxR, g_lenR, CAP_PP, g_dinvRd, g_dinvRp, g_bp1, 0, g_accd, 0, 0.f, 0, 0, D_NUM);
    spmm_dev(g_idxRT, g_curRT, CAP_DD, g_dinvRp, g_dinvRd, g_bdx, 0, g_accp, 0, 0.f, 0, 0, P_NUM);
    spmm_dev(g_idxR, g_lenR, CAP_PP, g_dinvRd, g_dinvRp, g_bpx, g_bdy, 0, 0, 0.f, 0, 0, D_NUM);
    gsync(target);

    // ---- P9: bipartite step 3 (finalize dru_int / pro_int)
    spmm_dev(g_idxR, g_lenR, CAP_PP, g_dinvRd, g_dinvRp, g_bp2, 0, g_accd, g_dru_int, 0.25f, 0, 0, D_NUM);
    spmm_dev(g_idxRT, g_curRT, CAP_DD, g_dinvRp, g_dinvRd, g_bdy, 0, g_accp, g_pro_int, 0.25f, 0, 0, P_NUM);
    gsync(target);

    // ---- P10: attention heads
    att_dev(g_dru_int, WA_drug, BA_drug, HA_drug, g_wdrug, D_NUM, sbuf);
    att_dev(g_pro_int, WA_pro, BA_pro, HA_pro, g_wpro, P_NUM, sbuf);
    att_dev(g_emb2, WB_drug, BB_drug, HB_drug, g_wdrel, D_NUM, sbuf);
    att_dev(g_emb3, WB_pro, BB_pro, HB_pro, g_wprel, P_NUM, sbuf);
    att_dev(g_emb4, WA_sim, BA_sim, HA_sim, g_wdsim, D_NUM, sbuf);
    gsync(target);

    // ---- P11: log-softmax (5 heads, 5 blocks)
    if (blockIdx.x < 5) {
        float* s; int n;
        switch (blockIdx.x) {
            case 0: s = g_wdrug; n = D_NUM; break;
            case 1: s = g_wpro;  n = P_NUM; break;
            case 2: s = g_wdrel; n = D_NUM; break;
            case 3: s = g_wprel; n = P_NUM; break;
            default:s = g_wdsim; n = D_NUM; break;
        }
        ls_dev(s, n, sbuf);
    }
    gsync(target);

    // ---- P12: weighted combine
    {
        int stride = gridDim.x * blockDim.x;
        for (int i = blockIdx.x * blockDim.x + threadIdx.x; i < DB + PB; i += stride) {
            if (i < DB) {
                int r = i >> 7;
                float wa = g_wdrug[r], wb = g_wdrel[r], wc = g_wdsim[r];
                float a = wa / (wa + wb + wc);
                float b = wb / (a + wb + wc);
                float c = 1.0f - a - b;
                g_fin_d[i] = a * g_dru_int[i] + b * g_emb2[i] + c * g_emb4[i];
            } else {
                int j = i - DB;
                int r = j >> 7;
                float wa = g_wpro[r], wb = g_wprel[r];
                float pa = wa / (wa + wb);
                g_fin_p[j] = pa * g_pro_int[j] + (1.0f - pa) * g_emb3[j];
            }
        }
    }
}

// ---------------- final GEMM + standardize + sigmoid ----------------
__global__ void __launch_bounds__(256) k_final_gemm() {
    __shared__ __align__(16) float sA[32 * 132];
    __shared__ __align__(16) float sB[32 * 132];
    int bi = blockIdx.y * 128, bj = blockIdx.x * 128;
    int t = threadIdx.x;
    int tx = t & 15, ty = t >> 4;
    int m0 = ty * 8, n0 = tx * 8;
    float acc[8][8];
#pragma unroll
    for (int i = 0; i < 8; i++)
#pragma unroll
        for (int j = 0; j < 8; j++) acc[i][j] = 0.0f;

    for (int k0 = 0; k0 < EMB; k0 += 32) {
#pragma unroll
        for (int it = 0; it < 4; it++) {
            int e = t + it * 256;
            int rr = e >> 3, kv = e & 7;
            int gi = bi + rr, gj = bj + rr;
            float4 va = (gi < D_NUM) ? *(const float4*)&g_fin_d[(size_t)gi * EMB + k0 + kv * 4]
                                     : make_float4(0.f, 0.f, 0.f, 0.f);
            float4 vb = (gj < P_NUM) ? *(const float4*)&g_fin_p[(size_t)gj * EMB + k0 + kv * 4]
                                     : make_float4(0.f, 0.f, 0.f, 0.f);
            sA[(kv * 4 + 0) * 132 + rr] = va.x;
            sA[(kv * 4 + 1) * 132 + rr] = va.y;
            sA[(kv * 4 + 2) * 132 + rr] = va.z;
            sA[(kv * 4 + 3) * 132 + rr] = va.w;
            sB[(kv * 4 + 0) * 132 + rr] = vb.x;
            sB[(kv * 4 + 1) * 132 + rr] = vb.y;
            sB[(kv * 4 + 2) * 132 + rr] = vb.z;
            sB[(kv * 4 + 3) * 132 + rr] = vb.w;
        }
        __syncthreads();
#pragma unroll
        for (int kk = 0; kk < 32; kk++) {
            const float* pa = &sA[kk * 132 + m0];
            const float* pb = &sB[kk * 132 + n0];
            float4 a0 = *(const float4*)pa;
            float4 a1 = *(const float4*)(pa + 4);
            float4 b0 = *(const float4*)pb;
            float4 b1 = *(const float4*)(pb + 4);
            float ra[8] = {a0.x, a0.y, a0.z, a0.w, a1.x, a1.y, a1.z, a1.w};
            float rb[8] = {b0.x, b0.y, b0.z, b0.w, b1.x, b1.y, b1.z, b1.w};
#pragma unroll
            for (int i = 0; i < 8; i++)
#pragma unroll
                for (int j = 0; j < 8; j++) acc[i][j] += ra[i] * rb[j];
        }
        __syncthreads();
    }
    double ls = 0.0, lq = 0.0;
#pragma unroll
    for (int i = 0; i < 8; i++) {
        int gi = bi + m0 + i;
        if (gi < D_NUM) {
#pragma unroll
            for (int j = 0; j < 8; j++) {
                int gj = bj + n0 + j;
                if (gj < P_NUM) {
                    float v = acc[i][j];
                    g_y[(size_t)gi * P_NUM + gj] = v;
                    ls += v;
                    lq += (double)v * v;
                }
            }
        }
    }
    __shared__ double sd[256];
    sd[t] = ls; __syncthreads();
    for (int o = 128; o; o >>= 1) { if (t < o) sd[t] += sd[t + o]; __syncthreads(); }
    if (t == 0) atomicAdd(&g_stats[0], sd[0]);
    __syncthreads();
    sd[t] = lq; __syncthreads();
    for (int o = 128; o; o >>= 1) { if (t < o) sd[t] += sd[t + o]; __syncthreads(); }
    if (t == 0) atomicAdd(&g_stats[1], sd[0]);
}

__global__ void k_finalize(float* __restrict__ out) {
    const double n = (double)D_NUM * (double)P_NUM;
    double sum = g_stats[0], sq = g_stats[1];
    double mean = sum / n;
    double var = (sq - sum * sum / n) / (n - 1.0);
    float istd = (float)(1.0 / sqrt(var));
    float mu = (float)mean;
    const size_t N4 = (size_t)D_NUM * P_NUM / 4;
    const float4* y4 = (const float4*)g_y;
    float4* o4 = (float4*)out;
    for (size_t i = (size_t)blockIdx.x * blockDim.x + threadIdx.x; i < N4;
         i += (size_t)gridDim.x * blockDim.x) {
        float4 v = y4[i];
        float4 o;
        o.x = 1.0f / (1.0f + expf(-(v.x - mu) * istd));
        o.y = 1.0f / (1.0f + expf(-(v.y - mu) * istd));
        o.z = 1.0f / (1.0f + expf(-(v.z - mu) * istd));
        o.w = 1.0f / (1.0f + expf(-(v.w - mu) * istd));
        o4[i] = o;
    }
}

// ---------------- host launcher ----------------
extern "C" void kernel_launch(void* const* d_in, const int* in_sizes, int n_in,
                              void* d_out, int out_size) {
    const float* A                 = (const float*)d_in[0];
    const float* drug_structure    = (const float*)d_in[1];
    const float* protein_structure = (const float*)d_in[2];
    const float* lin_drug_w = (const float*)d_in[3];
    const float* lin_drug_b = (const float*)d_in[4];
    const float* lin_pro_w  = (const float*)d_in[5];
    const float* lin_pro_b  = (const float*)d_in[6];
    const float* p_weight   = (const float*)d_in[7];
    const float* d_weight_i = (const float*)d_in[8];
    const float* pd_weight_p = (const float*)d_in[9];
    const float* pd_weight_d = (const float*)d_in[10];
    const float* dp_weight_p = (const float*)d_in[11];
    const float* WA_drug = (const float*)d_in[12];
    const float* BA_drug = (const float*)d_in[13];
    const float* HA_drug = (const float*)d_in[14];
    const float* WB_drug = (const float*)d_in[15];
    const float* BB_drug = (const float*)d_in[16];
    const float* HB_drug = (const float*)d_in[17];
    const float* WA_pro = (const float*)d_in[18];
    const float* BA_pro = (const float*)d_in[19];
    const float* HA_pro = (const float*)d_in[20];
    const float* WB_pro = (const float*)d_in[21];
    const float* BB_pro = (const float*)d_in[22];
    const float* HB_pro = (const float*)d_in[23];
    const float* WA_sim = (const float*)d_in[24];
    const float* BA_sim = (const float*)d_in[25];
    const float* HA_sim = (const float*)d_in[26];
    float* out = (float*)d_out;
    (void)in_sizes; (void)n_in; (void)out_size;

    void* tp;
    cudaGetSymbolAddress(&tp, g_curRT);  void* p_curRT  = tp;
    cudaGetSymbolAddress(&tp, g_stats);  void* p_stats  = tp;
    cudaGetSymbolAddress(&tp, g_barcnt); void* p_barcnt = tp;

    cudaMemsetAsync(p_curRT, 0, P_NUM * sizeof(int), 0);
    cudaMemsetAsync(p_stats, 0, 2 * sizeof(double), 0);
    cudaMemsetAsync(p_barcnt, 0, sizeof(unsigned), 0);

    k_ell_all<<<9000, 256>>>(A);

    k_mega<<<MEGA_BLKS, MEGA_THREADS>>>(
        drug_structure, protein_structure,
        lin_drug_w, lin_drug_b, lin_pro_w, lin_pro_b,
        p_weight, d_weight_i, pd_weight_p, pd_weight_d, dp_weight_p,
        WA_drug, BA_drug, HA_drug,
        WB_drug, BB_drug, HB_drug,
        WA_pro, BA_pro, HA_pro,
        WB_pro, BB_pro, HB_pro,
        WA_sim, BA_sim, HA_sim);

    dim3 fg((P_NUM + 127) / 128, (D_NUM + 127) / 128);
    k_final_gemm<<<fg, 256>>>();
    k_finalize<<<2048, 256>>>(out);
}